// round 10
// baseline (speedup 1.0000x reference)
#include <cuda_runtime.h>

// ---------------------------------------------------------------------------
// Problem constants + smem layout
// ---------------------------------------------------------------------------
namespace {
constexpr int   N    = 4096;
constexpr int   DIM  = 100;
constexpr int   HID  = 110;
constexpr int   T    = 50;
constexpr float DT   = 0.02f;
constexpr float EPS  = 1e-6f;
constexpr int   GRID = 128;       // co-resident blocks (1 per SM)
constexpr int   NT   = 512;       // threads per block
constexpr int   WS   = 112;       // weight tile col stride (16B aligned quads)

// smem offsets in floats
constexpr int OF_W1 = 0;                    // [100][112]
constexpr int OF_W2 = OF_W1 + DIM * WS;     // [110][112]
constexpr int OF_W3 = OF_W2 + HID * WS;     // [110][112]
constexpr int OF_X  = OF_W3 + HID * WS;     // [100][34]  x state  [k][r]
constexpr int OF_A  = OF_X + DIM * 34;      // [110][34]  h1 / h3 tile
constexpr int OF_B  = OF_A + HID * 34;      // [110][34]  h2 tile
constexpr int OF_D  = OF_B + HID * 34;      // [110][64]  duplicated gemm input
constexpr int OF_Y  = OF_D + HID * 64;      // [32]       y state
constexpr int OF_AF = OF_Y + 32;            // [112] affine a
constexpr int OF_BF = OF_AF + 112;          // [112] affine c
// resident per-feature parameters (loaded once)
constexpr int OF_P0W = OF_BF + 112;         // bn0w [100]
constexpr int OF_P0B = OF_P0W + DIM;        // bn0b [100]
constexpr int OF_P1W = OF_P0B + DIM;        // bn1w [110]
constexpr int OF_P1B = OF_P1W + HID;        // bn1b [110]
constexpr int OF_P2W = OF_P1B + HID;        // bn2w [110]
constexpr int OF_P2B = OF_P2W + HID;        // bn2b [110]
constexpr int OF_P3W = OF_P2B + HID;        // bn3w [100]
constexpr int OF_P3B = OF_P3W + DIM;        // bn3b [100]
constexpr int OF_B3  = OF_P3B + DIM;        // b3   [100]
constexpr int OF_ZI  = OF_B3 + DIM;         // zinit[100]
constexpr int SMF    = OF_ZI + DIM;         // 55056 floats = 220224 bytes
}

// ---------------------------------------------------------------------------
// Global state
// ---------------------------------------------------------------------------
__device__ float g_dwT[(size_t)T * N * DIM];   // dw transposed [T][N][DIM]
__device__ float g_s0[2 * DIM];
__device__ float g_s1[2 * HID];
__device__ float g_s2[2 * HID];
__device__ float g_s3[2 * DIM];
__device__ float g_acc[2];
__device__ unsigned g_cnt;
__device__ volatile unsigned g_gen;

__device__ __forceinline__ void affine_coef(float sum, float sumsq, float w,
                                            float b, float& a, float& c) {
    float mean = sum * (1.0f / N);
    float var  = fmaf(-mean, mean, sumsq * (1.0f / N)) + EPS;
    float r    = rsqrtf(var);
    r = r * (1.5f - 0.5f * var * r * r);   // Newton refine
    a = w * r;
    c = fmaf(-mean, a, b);
}

// flat grid barrier (R6-proven): all GRID blocks resident by construction
__device__ __forceinline__ void gbar(unsigned& target) {
    __syncthreads();
    if (threadIdx.x == 0) {
        __threadfence();
        if (atomicAdd(&g_cnt, 1u) == (unsigned)(GRID - 1)) {
            atomicExch(&g_cnt, 0u);
            __threadfence();
            g_gen = target;
        } else {
            while (g_gen < target) { __nanosleep(32); }
        }
        __threadfence();
    }
    __syncthreads();
    ++target;
}

#define FMA2(acc, a, b) \
    asm("fma.rn.f32x2 %0, %1, %2, %0;" : "+l"(acc) : "l"(a), "l"(b))

// ---------------------------------------------------------------------------
// Transpose dw [N*DIM, T] -> [T, N*DIM]; block (0,0) also resets global state
// ---------------------------------------------------------------------------
__global__ void transpose_dw(const float* __restrict__ in) {
    __shared__ float s[32][33];
    const int tx = threadIdx.x, ty = threadIdx.y;
    const int tid = ty * 32 + tx;
    if (blockIdx.x == 0 && blockIdx.y == 0) {
        for (int k = tid; k < 2 * DIM; k += 256) { g_s0[k] = 0.f; g_s3[k] = 0.f; }
        for (int k = tid; k < 2 * HID; k += 256) { g_s1[k] = 0.f; g_s2[k] = 0.f; }
        if (tid == 0) { g_acc[0] = 0.f; g_acc[1] = 0.f; g_cnt = 0u; g_gen = 0u; }
    }
    const int ij0 = blockIdx.x * 32;
    const int t0  = blockIdx.y * 32;
#pragma unroll
    for (int i = 0; i < 32; i += 8) {
        int t = t0 + tx;
        int ij = ij0 + ty + i;
        if (t < T) s[ty + i][tx] = in[(size_t)ij * T + t];
    }
    __syncthreads();
#pragma unroll
    for (int i = 0; i < 32; i += 8) {
        int t = t0 + ty + i;
        int ij = ij0 + tx;
        if (t < T) g_dwT[(size_t)t * (N * DIM) + ij] = s[tx][ty + i];
    }
}

// ---------------------------------------------------------------------------
// BN affine (+relu) on [K x 32] tile -> interleaved duplicated layout:
//   chunks 0..7  = row pairs {0,1},{4,5},...,{28,29}
//   chunks 8..15 = row pairs {2,3},{6,7},...,{30,31}
// ---------------------------------------------------------------------------
template <int K, bool RELU>
__device__ __forceinline__ void prep(const float* __restrict__ gStat,
                                     const float* __restrict__ bnw,
                                     const float* __restrict__ bnb,
                                     const float* __restrict__ src,
                                     float* __restrict__ dup,
                                     float* __restrict__ sAf,
                                     float* __restrict__ sBf) {
    const int tid = threadIdx.x;
    for (int k = tid; k < K; k += NT) {
        float a, c;
        affine_coef(__ldcg(&gStat[k]), __ldcg(&gStat[K + k]), bnw[k], bnb[k], a, c);
        sAf[k] = a; sBf[k] = c;
    }
    __syncthreads();
    for (int idx = tid; idx < K * 32; idx += NT) {
        int k = idx >> 5, r = idx & 31;
        float v = fmaf(src[k * 34 + r], sAf[k], sBf[k]);
        if (RELU) v = fmaxf(v, 0.f);
        int off = ((r & 2) ? 32 : 0) + (r >> 2) * 4 + (r & 1) * 2;
        *reinterpret_cast<float2*>(dup + (k << 6) + off) = make_float2(v, v);
    }
    __syncthreads();
}

// ---------------------------------------------------------------------------
// GEMM + fused BN-stat epilogue.
// 7 active warps, lane tile 4 rows x 4 cols; mainloop identical to R9.
// Epilogue: float2 stores (alignment-safe), then shfl-reduce sum/sumsq over
// the 8 row-group lanes and atomicAdd per column into gStat.
// ---------------------------------------------------------------------------
template <int K, int C, bool BIAS>
__device__ __forceinline__ void gemm(const float* __restrict__ sD,
                                     const float* __restrict__ sW,
                                     float* __restrict__ sO,
                                     const float* __restrict__ biasS,
                                     float* __restrict__ gStat) {
    const int warp = threadIdx.x >> 5, lane = threadIdx.x & 31;
    if (warp >= 7) return;
    const int g  = lane & 7;                         // row group: rows 4g..4g+3
    const int c0 = warp * 16 + ((lane >> 3) << 2);   // 4 cols, c0+3 <= 111
    const int r0 = 4 * g;

    unsigned long long acc[4][2];
#pragma unroll
    for (int r = 0; r < 4; ++r) { acc[r][0] = 0ull; acc[r][1] = 0ull; }

    const float* pD = sD + 4 * g;            // chunk g
    const float* pW = sW + c0;
#pragma unroll 2
    for (int k = 0; k < K; ++k) {
        ulonglong2 xa = *reinterpret_cast<const ulonglong2*>(pD);
        ulonglong2 xb = *reinterpret_cast<const ulonglong2*>(pD + 32);
        ulonglong2 w  = *reinterpret_cast<const ulonglong2*>(pW);
        FMA2(acc[0][0], w.x, xa.x);
        FMA2(acc[0][1], w.y, xa.x);
        FMA2(acc[1][0], w.x, xa.y);
        FMA2(acc[1][1], w.y, xa.y);
        FMA2(acc[2][0], w.x, xb.x);
        FMA2(acc[2][1], w.y, xb.x);
        FMA2(acc[3][0], w.x, xb.y);
        FMA2(acc[3][1], w.y, xb.y);
        pD += 64;
        pW += WS;
    }

    float v[4][4];
#pragma unroll
    for (int r = 0; r < 4; ++r) {
        asm("mov.b64 {%0,%1}, %2;" : "=f"(v[r][0]), "=f"(v[r][1]) : "l"(acc[r][0]));
        asm("mov.b64 {%0,%1}, %2;" : "=f"(v[r][2]), "=f"(v[r][3]) : "l"(acc[r][1]));
    }

    float s[4], q[4];
#pragma unroll
    for (int c = 0; c < 4; ++c) {
        const int col = c0 + c;
        float b = BIAS ? biasS[col < C ? col : 0] : 0.f;
        float v0 = v[0][c] + b, v1 = v[1][c] + b;
        float v2 = v[2][c] + b, v3 = v[3][c] + b;
        if (col < C) {
            float* dst = &sO[col * 34 + r0];           // even offset: 8B aligned
            *reinterpret_cast<float2*>(dst)     = make_float2(v0, v1);
            *reinterpret_cast<float2*>(dst + 2) = make_float2(v2, v3);
        }
        s[c] = (v0 + v1) + (v2 + v3);
        q[c] = fmaf(v0, v0, fmaf(v1, v1, fmaf(v2, v2, v3 * v3)));
    }
    // reduce across the 8 row-group lanes (lane bits 0..2)
#pragma unroll
    for (int o = 1; o < 8; o <<= 1) {
#pragma unroll
        for (int c = 0; c < 4; ++c) {
            s[c] += __shfl_xor_sync(~0u, s[c], o);
            q[c] += __shfl_xor_sync(~0u, q[c], o);
        }
    }
    if ((lane & 7) == 0) {
#pragma unroll
        for (int c = 0; c < 4; ++c) {
            const int col = c0 + c;
            if (col < C) {
                atomicAdd(&gStat[col], s[c]);
                atomicAdd(&gStat[C + col], q[c]);
            }
        }
    }
}

// per-column sum / sumsq over [DIM x 32] tile (phase A / x only)
template <int C>
__device__ __forceinline__ void statp(const float* __restrict__ sO,
                                      float* __restrict__ gStat) {
    const int tid = threadIdx.x;
    if (tid < C) {
        float s = 0.f, q = 0.f;
#pragma unroll
        for (int r = 0; r < 32; r += 2) {
            float2 v = *reinterpret_cast<const float2*>(&sO[tid * 34 + r]);
            s += v.x + v.y;
            q = fmaf(v.x, v.x, fmaf(v.y, v.y, q));
        }
        atomicAdd(&gStat[tid], s);
        atomicAdd(&gStat[C + tid], q);
    }
}

// spread-zero: each block clears its slice (<=2 stores, 1 thread)
template <int SZ>
__device__ __forceinline__ void zero_spread(float* __restrict__ gStat) {
    if (threadIdx.x == 0)
        for (int k = blockIdx.x; k < SZ; k += GRID) __stcg(&gStat[k], 0.f);
}

// ---------------------------------------------------------------------------
// The persistent kernel: all 50 steps in one launch
// ---------------------------------------------------------------------------
__global__ void __launch_bounds__(NT, 1) persistK(
    const float* __restrict__ zinit, const float* __restrict__ yinit,
    const float* __restrict__ bn0w, const float* __restrict__ bn0b,
    const float* __restrict__ w1,   const float* __restrict__ bn1w,
    const float* __restrict__ bn1b, const float* __restrict__ w2,
    const float* __restrict__ bn2w, const float* __restrict__ bn2b,
    const float* __restrict__ w3,   const float* __restrict__ b3,
    const float* __restrict__ bn3w, const float* __restrict__ bn3b,
    float* __restrict__ out_loss, float* __restrict__ out_y,
    float* __restrict__ out_ye,   float* __restrict__ out_xs,
    float* __restrict__ out_us)
{
    extern __shared__ float sm[];
    float* sW1 = sm + OF_W1;
    float* sW2 = sm + OF_W2;
    float* sW3 = sm + OF_W3;
    float* sX  = sm + OF_X;
    float* sTa = sm + OF_A;
    float* sTb = sm + OF_B;
    float* sD  = sm + OF_D;
    float* sy  = sm + OF_Y;
    float* sAf = sm + OF_AF;
    float* sBf = sm + OF_BF;

    const int tid   = threadIdx.x;
    const int warp  = tid >> 5, lane = tid & 31;
    const int rbase = blockIdx.x * 32;
    unsigned target = 1;

    // zero weight region (pads) + x state
    for (int i = tid; i < OF_X; i += NT) sm[i] = 0.f;
    for (int i = tid; i < DIM * 34; i += NT) sX[i] = 0.f;
    __syncthreads();
    // load weights once: sW[k*WS + c] = W[c*K + k]
    for (int idx = tid; idx < HID * DIM; idx += NT) {   // W1 [110,100]
        int c = idx / DIM, k = idx - c * DIM;
        sW1[k * WS + c] = w1[idx];
    }
    for (int idx = tid; idx < HID * HID; idx += NT) {   // W2 [110,110]
        int c = idx / HID, k = idx - c * HID;
        sW2[k * WS + c] = w2[idx];
    }
    for (int idx = tid; idx < DIM * HID; idx += NT) {   // W3 [100,110]
        int c = idx / HID, k = idx - c * HID;
        sW3[k * WS + c] = w3[idx];
    }
    // resident per-feature params
    if (tid < DIM) {
        sm[OF_P0W + tid] = bn0w[tid];
        sm[OF_P0B + tid] = bn0b[tid];
        sm[OF_P3W + tid] = bn3w[tid];
        sm[OF_P3B + tid] = bn3b[tid];
        sm[OF_B3  + tid] = b3[tid];
        sm[OF_ZI  + tid] = zinit[tid];
    } else if (tid >= 128 && tid < 128 + HID) {
        int k = tid - 128;
        sm[OF_P1W + k] = bn1w[k];
        sm[OF_P1B + k] = bn1b[k];
    } else if (tid >= 256 && tid < 256 + HID) {
        int k = tid - 256;
        sm[OF_P2W + k] = bn2w[k];
        sm[OF_P2B + k] = bn2b[k];
    }
    const float y0 = yinit[0];

    for (int t = 0; t < T; ++t) {
        const bool first = (t == 0), last = (t == T - 1);

        // ---------------- phase A ----------------
        if (!first) {
            for (int k = tid; k < DIM; k += NT) {
                float a, c;
                affine_coef(__ldcg(&g_s3[k]), __ldcg(&g_s3[DIM + k]),
                            sm[OF_P3W + k], sm[OF_P3B + k], a, c);
                sAf[k] = a * 1e-4f;   // /DIM (subnet) * /DIM (z update)
                sBf[k] = c * 1e-4f;
            }
        }
        if (!last) zero_spread<2 * HID>(g_s2);
        __syncthreads();

        const float* dwt = g_dwT + ((size_t)t * N + rbase) * DIM;
        float* xsO = out_xs + ((size_t)t * N + rbase) * DIM;

        // hoisted dw loads for both row iterations (MLP = 8)
        float dwv[2][4];
#pragma unroll
        for (int it = 0; it < 2; ++it) {
            const int r = it * 16 + warp;
#pragma unroll
            for (int c2 = 0; c2 < 4; ++c2) {
                int j = lane + 32 * c2;
                dwv[it][c2] = (j < DIM) ? dwt[(size_t)r * DIM + j] : 0.f;
            }
        }

#pragma unroll
        for (int it = 0; it < 2; ++it) {
            const int r = it * 16 + warp;
            const int i = rbase + r;
            float sz = 0.f, zdw = 0.f, xx = 0.f;
            float xo[4];
#pragma unroll
            for (int c2 = 0; c2 < 4; ++c2) {
                int j = lane + 32 * c2;
                xo[c2] = 0.f;
                if (j < DIM) {
                    float z = first ? sm[OF_ZI + j]
                                    : fmaf(sTa[j * 34 + r], sAf[j], sBf[j]);
                    xo[c2] = sX[j * 34 + r];
                    sz  += z;
                    zdw += z * dwv[it][c2];
                    xx  += xo[c2] * xo[c2];
                }
            }
#pragma unroll
            for (int o = 16; o; o >>= 1) {
                sz  += __shfl_xor_sync(~0u, sz, o);
                zdw += __shfl_xor_sync(~0u, zdw, o);
                xx  += __shfl_xor_sync(~0u, xx, o);
            }
            const float u = fminf(fmaxf(-sz, -1.f), 1.f);
            float yv = first ? y0 : sy[r];
            yv = yv - DT * 0.5f * (xx + u * u) + DT * sz * u + zdw;
            if (lane == 0) {
                out_us[(size_t)t * N + i] = u;
                if (last) {
                    out_y[i] = yv;
                    float ye = 0.5f * xx;
                    out_ye[i] = ye;
                    float d = yv - ye, ad = fabsf(d);
                    atomicAdd(&g_acc[0], (ad < 1.f) ? 0.5f * d * d : ad - 0.5f);
                    atomicAdd(&g_acc[1], ye);
                } else {
                    sy[r] = yv;
                }
            }
#pragma unroll
            for (int c2 = 0; c2 < 4; ++c2) {
                int j = lane + 32 * c2;
                if (j < DIM) {
                    xsO[(size_t)r * DIM + j] = xo[c2];
                    if (!last)
                        sX[j * 34 + r] = fmaf(xo[c2], 1.f - DT,
                                              fmaf(u, DT, dwv[it][c2]));
                }
            }
        }
        __syncthreads();

        if (last) {
            gbar(target);
            if (blockIdx.x == 0 && tid == 0) {
                float m1 = __ldcg(&g_acc[0]) * (1.0f / N);
                float m2 = __ldcg(&g_acc[1]) * (1.0f / N);
                out_loss[0] = 100.0f * (m1 + m2 * m2);
            }
            break;
        }

        statp<DIM>(sX, g_s0);
        gbar(target);

        // ---------------- GEMM1: h1 = bn0(x) @ W1^T ----------------
        zero_spread<2 * DIM>(g_s3);
        prep<DIM, false>(g_s0, sm + OF_P0W, sm + OF_P0B, sX, sD, sAf, sBf);
        gemm<DIM, HID, false>(sD, sW1, sTa, nullptr, g_s1);
        gbar(target);

        // ---------------- GEMM2: h2 = relu(bn1(h1)) @ W2^T ----------------
        zero_spread<2 * DIM>(g_s0);
        prep<HID, true>(g_s1, sm + OF_P1W, sm + OF_P1B, sTa, sD, sAf, sBf);
        gemm<HID, HID, false>(sD, sW2, sTb, nullptr, g_s2);
        gbar(target);

        // ---------------- GEMM3: h3 = relu(bn2(h2)) @ W3^T + b3 --------
        zero_spread<2 * HID>(g_s1);
        prep<HID, true>(g_s2, sm + OF_P2W, sm + OF_P2B, sTb, sD, sAf, sBf);
        gemm<HID, DIM, true>(sD, sW3, sTa, sm + OF_B3, g_s3);
        gbar(target);
    }
}

// ---------------------------------------------------------------------------
// Launcher
// ---------------------------------------------------------------------------
extern "C" void kernel_launch(void* const* d_in, const int* in_sizes, int n_in,
                              void* d_out, int out_size) {
    const float* dw    = (const float*)d_in[0];
    const float* yinit = (const float*)d_in[1];
    const float* zinit = (const float*)d_in[2];
    const float* bn0w  = (const float*)d_in[3];
    const float* bn0b  = (const float*)d_in[4];
    const float* w1    = (const float*)d_in[5];
    const float* bn1w  = (const float*)d_in[6];
    const float* bn1b  = (const float*)d_in[7];
    const float* w2    = (const float*)d_in[8];
    const float* bn2w  = (const float*)d_in[9];
    const float* bn2b  = (const float*)d_in[10];
    const float* w3    = (const float*)d_in[11];
    const float* b3    = (const float*)d_in[12];
    const float* bn3w  = (const float*)d_in[13];
    const float* bn3b  = (const float*)d_in[14];

    float* out    = (float*)d_out;
    float* out_y  = out + 1;
    float* out_ye = out + 1 + N;
    float* out_xs = out + 1 + 2 * N;
    float* out_us = out_xs + (size_t)T * N * DIM;

    cudaFuncSetAttribute(persistK,
                         cudaFuncAttributeMaxDynamicSharedMemorySize,
                         SMF * (int)sizeof(float));

    transpose_dw<<<dim3(N * DIM / 32, 2), dim3(32, 8)>>>(dw);
    persistK<<<GRID, NT, SMF * sizeof(float)>>>(
        zinit, yinit, bn0w, bn0b, w1, bn1w, bn1b, w2, bn2w, bn2b,
        w3, b3, bn3w, bn3b, out, out_y, out_ye, out_xs, out_us);
}

// round 11
// speedup vs baseline: 1.4224x; 1.4224x over previous
#include <cuda_runtime.h>

// ---------------------------------------------------------------------------
// Problem constants + smem layout
// ---------------------------------------------------------------------------
namespace {
constexpr int   N    = 4096;
constexpr int   DIM  = 100;
constexpr int   HID  = 110;
constexpr int   T    = 50;
constexpr float DT   = 0.02f;
constexpr float EPS  = 1e-6f;
constexpr int   GRID = 128;       // co-resident blocks (1 per SM)
constexpr int   NT   = 512;       // threads per block
constexpr int   WS   = 112;       // weight tile col stride (16B aligned quads)

// smem offsets in floats
constexpr int OF_W1 = 0;                    // [100][112]
constexpr int OF_W2 = OF_W1 + DIM * WS;     // [110][112]
constexpr int OF_W3 = OF_W2 + HID * WS;     // [110][112]
constexpr int OF_X  = OF_W3 + HID * WS;     // [100][34]  x state  [k][r]
constexpr int OF_A  = OF_X + DIM * 34;      // [110][34]  h1 / h3 tile
constexpr int OF_B  = OF_A + HID * 34;      // [110][34]  h2 tile
constexpr int OF_D  = OF_B + HID * 34;      // [110][64]  duplicated gemm input
constexpr int OF_Y  = OF_D + HID * 64;      // [32]       y state
constexpr int OF_AF = OF_Y + 32;            // [112] affine a
constexpr int OF_BF = OF_AF + 112;          // [112] affine c
// resident per-feature parameters (loaded once)
constexpr int OF_P0W = OF_BF + 112;         // bn0w [100]
constexpr int OF_P0B = OF_P0W + DIM;        // bn0b [100]
constexpr int OF_P1W = OF_P0B + DIM;        // bn1w [110]
constexpr int OF_P1B = OF_P1W + HID;        // bn1b [110]
constexpr int OF_P2W = OF_P1B + HID;        // bn2w [110]
constexpr int OF_P2B = OF_P2W + HID;        // bn2b [110]
constexpr int OF_P3W = OF_P2B + HID;        // bn3w [100]
constexpr int OF_P3B = OF_P3W + DIM;        // bn3b [100]
constexpr int OF_B3  = OF_P3B + DIM;        // b3   [100]
constexpr int OF_ZI  = OF_B3 + DIM;         // zinit[100]
constexpr int SMF    = OF_ZI + DIM;         // 55056 floats = 220224 bytes
}

// ---------------------------------------------------------------------------
// Global state
// ---------------------------------------------------------------------------
__device__ float g_dwT[(size_t)T * N * DIM];   // dw transposed [T][N][DIM]
__device__ float g_s0[2 * DIM];
__device__ float g_s1[2 * HID];
__device__ float g_s2[2 * HID];
__device__ float g_s3[2 * DIM];
__device__ float g_acc[2];
__device__ unsigned g_cnt;
__device__ volatile unsigned g_gen;

__device__ __forceinline__ void affine_coef(float sum, float sumsq, float w,
                                            float b, float& a, float& c) {
    float mean = sum * (1.0f / N);
    float var  = fmaf(-mean, mean, sumsq * (1.0f / N)) + EPS;
    float r    = rsqrtf(var);
    r = r * (1.5f - 0.5f * var * r * r);   // Newton refine
    a = w * r;
    c = fmaf(-mean, a, b);
}

// flat grid barrier (R6-proven): all GRID blocks resident by construction
__device__ __forceinline__ void gbar(unsigned& target) {
    __syncthreads();
    if (threadIdx.x == 0) {
        __threadfence();
        if (atomicAdd(&g_cnt, 1u) == (unsigned)(GRID - 1)) {
            atomicExch(&g_cnt, 0u);
            __threadfence();
            g_gen = target;
        } else {
            while (g_gen < target) { __nanosleep(32); }
        }
        __threadfence();
    }
    __syncthreads();
    ++target;
}

#define FMA2(acc, a, b) \
    asm("fma.rn.f32x2 %0, %1, %2, %0;" : "+l"(acc) : "l"(a), "l"(b))

// ---------------------------------------------------------------------------
// Transpose dw [N*DIM, T] -> [T, N*DIM]; block (0,0) also resets global state
// ---------------------------------------------------------------------------
__global__ void transpose_dw(const float* __restrict__ in) {
    __shared__ float s[32][33];
    const int tx = threadIdx.x, ty = threadIdx.y;
    const int tid = ty * 32 + tx;
    if (blockIdx.x == 0 && blockIdx.y == 0) {
        for (int k = tid; k < 2 * DIM; k += 256) { g_s0[k] = 0.f; g_s3[k] = 0.f; }
        for (int k = tid; k < 2 * HID; k += 256) { g_s1[k] = 0.f; g_s2[k] = 0.f; }
        if (tid == 0) { g_acc[0] = 0.f; g_acc[1] = 0.f; g_cnt = 0u; g_gen = 0u; }
    }
    const int ij0 = blockIdx.x * 32;
    const int t0  = blockIdx.y * 32;
#pragma unroll
    for (int i = 0; i < 32; i += 8) {
        int t = t0 + tx;
        int ij = ij0 + ty + i;
        if (t < T) s[ty + i][tx] = in[(size_t)ij * T + t];
    }
    __syncthreads();
#pragma unroll
    for (int i = 0; i < 32; i += 8) {
        int t = t0 + ty + i;
        int ij = ij0 + tx;
        if (t < T) g_dwT[(size_t)t * (N * DIM) + ij] = s[tx][ty + i];
    }
}

// ---------------------------------------------------------------------------
// BN affine (+relu) on [K x 32] tile -> interleaved duplicated layout:
//   chunks 0..7  = row pairs {0,1},{4,5},...,{28,29}
//   chunks 8..15 = row pairs {2,3},{6,7},...,{30,31}
// ---------------------------------------------------------------------------
template <int K, bool RELU>
__device__ __forceinline__ void prep(const float* __restrict__ gStat,
                                     const float* __restrict__ bnw,
                                     const float* __restrict__ bnb,
                                     const float* __restrict__ src,
                                     float* __restrict__ dup,
                                     float* __restrict__ sAf,
                                     float* __restrict__ sBf) {
    const int tid = threadIdx.x;
    for (int k = tid; k < K; k += NT) {
        float a, c;
        affine_coef(__ldcg(&gStat[k]), __ldcg(&gStat[K + k]), bnw[k], bnb[k], a, c);
        sAf[k] = a; sBf[k] = c;
    }
    __syncthreads();
    for (int idx = tid; idx < K * 32; idx += NT) {
        int k = idx >> 5, r = idx & 31;
        float v = fmaf(src[k * 34 + r], sAf[k], sBf[k]);
        if (RELU) v = fmaxf(v, 0.f);
        int off = ((r & 2) ? 32 : 0) + (r >> 2) * 4 + (r & 1) * 2;
        *reinterpret_cast<float2*>(dup + (k << 6) + off) = make_float2(v, v);
    }
    __syncthreads();
}

// ---------------------------------------------------------------------------
// GEMM: sO[c*34+r] = sum_k dup[k][r] * sW[k*WS+c]  (+ biasS[c] from smem)
// 7 active warps, lane tile 4 rows x 4 cols; float2-only epilogue stores.
// ---------------------------------------------------------------------------
template <int K, int C, bool BIAS>
__device__ __forceinline__ void gemm(const float* __restrict__ sD,
                                     const float* __restrict__ sW,
                                     float* __restrict__ sO,
                                     const float* __restrict__ biasS) {
    const int warp = threadIdx.x >> 5, lane = threadIdx.x & 31;
    if (warp >= 7) return;
    const int g  = lane & 7;                         // row group: rows 4g..4g+3
    const int c0 = warp * 16 + ((lane >> 3) << 2);   // 4 cols, c0+3 <= 111
    const int r0 = 4 * g;

    unsigned long long acc[4][2];
#pragma unroll
    for (int r = 0; r < 4; ++r) { acc[r][0] = 0ull; acc[r][1] = 0ull; }

    const float* pD = sD + 4 * g;            // chunk g
    const float* pW = sW + c0;
#pragma unroll 2
    for (int k = 0; k < K; ++k) {
        ulonglong2 xa = *reinterpret_cast<const ulonglong2*>(pD);
        ulonglong2 xb = *reinterpret_cast<const ulonglong2*>(pD + 32);
        ulonglong2 w  = *reinterpret_cast<const ulonglong2*>(pW);
        FMA2(acc[0][0], w.x, xa.x);
        FMA2(acc[0][1], w.y, xa.x);
        FMA2(acc[1][0], w.x, xa.y);
        FMA2(acc[1][1], w.y, xa.y);
        FMA2(acc[2][0], w.x, xb.x);
        FMA2(acc[2][1], w.y, xb.x);
        FMA2(acc[3][0], w.x, xb.y);
        FMA2(acc[3][1], w.y, xb.y);
        pD += 64;
        pW += WS;
    }

    float v[4][4];
#pragma unroll
    for (int r = 0; r < 4; ++r) {
        asm("mov.b64 {%0,%1}, %2;" : "=f"(v[r][0]), "=f"(v[r][1]) : "l"(acc[r][0]));
        asm("mov.b64 {%0,%1}, %2;" : "=f"(v[r][2]), "=f"(v[r][3]) : "l"(acc[r][1]));
    }
#pragma unroll
    for (int c = 0; c < 4; ++c) {
        const int col = c0 + c;
        if (col < C) {
            float b = BIAS ? biasS[col] : 0.f;
            float* dst = &sO[col * 34 + r0];           // even offset: 8B aligned
            *reinterpret_cast<float2*>(dst)     = make_float2(v[0][c] + b, v[1][c] + b);
            *reinterpret_cast<float2*>(dst + 2) = make_float2(v[2][c] + b, v[3][c] + b);
        }
    }
}

// per-column sum / sumsq over [C x 32] tile -> global RED
template <int C>
__device__ __forceinline__ void statp(const float* __restrict__ sO,
                                      float* __restrict__ gStat) {
    const int tid = threadIdx.x;
    if (tid < C) {
        float s = 0.f, q = 0.f;
#pragma unroll
        for (int r = 0; r < 32; r += 2) {
            float2 v = *reinterpret_cast<const float2*>(&sO[tid * 34 + r]);
            s += v.x + v.y;
            q = fmaf(v.x, v.x, fmaf(v.y, v.y, q));
        }
        atomicAdd(&gStat[tid], s);
        atomicAdd(&gStat[C + tid], q);
    }
}

// ---------------------------------------------------------------------------
// The persistent kernel: all 50 steps in one launch
// ---------------------------------------------------------------------------
__global__ void __launch_bounds__(NT, 1) persistK(
    const float* __restrict__ zinit, const float* __restrict__ yinit,
    const float* __restrict__ bn0w, const float* __restrict__ bn0b,
    const float* __restrict__ w1,   const float* __restrict__ bn1w,
    const float* __restrict__ bn1b, const float* __restrict__ w2,
    const float* __restrict__ bn2w, const float* __restrict__ bn2b,
    const float* __restrict__ w3,   const float* __restrict__ b3,
    const float* __restrict__ bn3w, const float* __restrict__ bn3b,
    float* __restrict__ out_loss, float* __restrict__ out_y,
    float* __restrict__ out_ye,   float* __restrict__ out_xs,
    float* __restrict__ out_us)
{
    extern __shared__ float sm[];
    float* sW1 = sm + OF_W1;
    float* sW2 = sm + OF_W2;
    float* sW3 = sm + OF_W3;
    float* sX  = sm + OF_X;
    float* sTa = sm + OF_A;
    float* sTb = sm + OF_B;
    float* sD  = sm + OF_D;
    float* sy  = sm + OF_Y;
    float* sAf = sm + OF_AF;
    float* sBf = sm + OF_BF;

    const int tid   = threadIdx.x;
    const int warp  = tid >> 5, lane = tid & 31;
    const int rbase = blockIdx.x * 32;
    unsigned target = 1;

    // zero weight region (pads) + x state
    for (int i = tid; i < OF_X; i += NT) sm[i] = 0.f;
    for (int i = tid; i < DIM * 34; i += NT) sX[i] = 0.f;
    __syncthreads();
    // load weights once: sW[k*WS + c] = W[c*K + k]
    for (int idx = tid; idx < HID * DIM; idx += NT) {   // W1 [110,100]
        int c = idx / DIM, k = idx - c * DIM;
        sW1[k * WS + c] = w1[idx];
    }
    for (int idx = tid; idx < HID * HID; idx += NT) {   // W2 [110,110]
        int c = idx / HID, k = idx - c * HID;
        sW2[k * WS + c] = w2[idx];
    }
    for (int idx = tid; idx < DIM * HID; idx += NT) {   // W3 [100,110]
        int c = idx / HID, k = idx - c * HID;
        sW3[k * WS + c] = w3[idx];
    }
    // resident per-feature params (loaded once)
    if (tid < DIM) {
        sm[OF_P0W + tid] = bn0w[tid];
        sm[OF_P0B + tid] = bn0b[tid];
        sm[OF_P3W + tid] = bn3w[tid];
        sm[OF_P3B + tid] = bn3b[tid];
        sm[OF_B3  + tid] = b3[tid];
        sm[OF_ZI  + tid] = zinit[tid];
    } else if (tid >= 128 && tid < 128 + HID) {
        int k = tid - 128;
        sm[OF_P1W + k] = bn1w[k];
        sm[OF_P1B + k] = bn1b[k];
    } else if (tid >= 256 && tid < 256 + HID) {
        int k = tid - 256;
        sm[OF_P2W + k] = bn2w[k];
        sm[OF_P2B + k] = bn2b[k];
    }
    const float y0 = yinit[0];

    for (int t = 0; t < T; ++t) {
        const bool first = (t == 0), last = (t == T - 1);

        // ---------------- phase A ----------------
        if (!first) {
            for (int k = tid; k < DIM; k += NT) {
                float a, c;
                affine_coef(__ldcg(&g_s3[k]), __ldcg(&g_s3[DIM + k]),
                            sm[OF_P3W + k], sm[OF_P3B + k], a, c);
                sAf[k] = a * 1e-4f;   // /DIM (subnet) * /DIM (z update)
                sBf[k] = c * 1e-4f;
            }
        }
        if (!last && blockIdx.x == 0)
            for (int k = tid; k < 2 * HID; k += NT) __stcg(&g_s2[k], 0.f);
        __syncthreads();

        const float* dwt = g_dwT + ((size_t)t * N + rbase) * DIM;
        float* xsO = out_xs + ((size_t)t * N + rbase) * DIM;

#pragma unroll
        for (int it = 0; it < 2; ++it) {
            const int r = it * 16 + warp;
            const int i = rbase + r;
            float sz = 0.f, zdw = 0.f, xx = 0.f;
            float xo[4], dwv[4];
#pragma unroll
            for (int c2 = 0; c2 < 4; ++c2) {
                int j = lane + 32 * c2;
                xo[c2] = 0.f; dwv[c2] = 0.f;
                if (j < DIM) {
                    float z = first ? sm[OF_ZI + j]
                                    : fmaf(sTa[j * 34 + r], sAf[j], sBf[j]);
                    dwv[c2] = dwt[(size_t)r * DIM + j];
                    xo[c2]  = sX[j * 34 + r];
                    sz  += z;
                    zdw += z * dwv[c2];
                    xx  += xo[c2] * xo[c2];
                }
            }
#pragma unroll
            for (int o = 16; o; o >>= 1) {
                sz  += __shfl_xor_sync(~0u, sz, o);
                zdw += __shfl_xor_sync(~0u, zdw, o);
                xx  += __shfl_xor_sync(~0u, xx, o);
            }
            const float u = fminf(fmaxf(-sz, -1.f), 1.f);
            float yv = first ? y0 : sy[r];
            yv = yv - DT * 0.5f * (xx + u * u) + DT * sz * u + zdw;
            if (lane == 0) {
                out_us[(size_t)t * N + i] = u;
                if (last) {
                    out_y[i] = yv;
                    float ye = 0.5f * xx;
                    out_ye[i] = ye;
                    float d = yv - ye, ad = fabsf(d);
                    atomicAdd(&g_acc[0], (ad < 1.f) ? 0.5f * d * d : ad - 0.5f);
                    atomicAdd(&g_acc[1], ye);
                } else {
                    sy[r] = yv;
                }
            }
#pragma unroll
            for (int c2 = 0; c2 < 4; ++c2) {
                int j = lane + 32 * c2;
                if (j < DIM) {
                    xsO[(size_t)r * DIM + j] = xo[c2];
                    if (!last)
                        sX[j * 34 + r] = fmaf(xo[c2], 1.f - DT,
                                              fmaf(u, DT, dwv[c2]));
                }
            }
        }
        __syncthreads();

        if (last) {
            gbar(target);
            if (blockIdx.x == 0 && tid == 0) {
                float m1 = __ldcg(&g_acc[0]) * (1.0f / N);
                float m2 = __ldcg(&g_acc[1]) * (1.0f / N);
                out_loss[0] = 100.0f * (m1 + m2 * m2);
            }
            break;
        }

        statp<DIM>(sX, g_s0);
        gbar(target);

        // ---------------- GEMM1: h1 = bn0(x) @ W1^T ----------------
        if (blockIdx.x == 0)
            for (int k = tid; k < 2 * DIM; k += NT) __stcg(&g_s3[k], 0.f);
        prep<DIM, false>(g_s0, sm + OF_P0W, sm + OF_P0B, sX, sD, sAf, sBf);
        gemm<DIM, HID, false>(sD, sW1, sTa, nullptr);
        __syncthreads();
        statp<HID>(sTa, g_s1);
        gbar(target);

        // ---------------- GEMM2: h2 = relu(bn1(h1)) @ W2^T ----------------
        if (blockIdx.x == 0)
            for (int k = tid; k < 2 * DIM; k += NT) __stcg(&g_s0[k], 0.f);
        prep<HID, true>(g_s1, sm + OF_P1W, sm + OF_P1B, sTa, sD, sAf, sBf);
        gemm<HID, HID, false>(sD, sW2, sTb, nullptr);
        __syncthreads();
        statp<HID>(sTb, g_s2);
        gbar(target);

        // ---------------- GEMM3: h3 = relu(bn2(h2)) @ W3^T + b3 --------
        if (blockIdx.x == 0)
            for (int k = tid; k < 2 * HID; k += NT) __stcg(&g_s1[k], 0.f);
        prep<HID, true>(g_s2, sm + OF_P2W, sm + OF_P2B, sTb, sD, sAf, sBf);
        gemm<HID, DIM, true>(sD, sW3, sTa, sm + OF_B3);
        __syncthreads();
        statp<DIM>(sTa, g_s3);
        gbar(target);
    }
}

// ---------------------------------------------------------------------------
// Launcher
// ---------------------------------------------------------------------------
extern "C" void kernel_launch(void* const* d_in, const int* in_sizes, int n_in,
                              void* d_out, int out_size) {
    const float* dw    = (const float*)d_in[0];
    const float* yinit = (const float*)d_in[1];
    const float* zinit = (const float*)d_in[2];
    const float* bn0w  = (const float*)d_in[3];
    const float* bn0b  = (const float*)d_in[4];
    const float* w1    = (const float*)d_in[5];
    const float* bn1w  = (const float*)d_in[6];
    const float* bn1b  = (const float*)d_in[7];
    const float* w2    = (const float*)d_in[8];
    const float* bn2w  = (const float*)d_in[9];
    const float* bn2b  = (const float*)d_in[10];
    const float* w3    = (const float*)d_in[11];
    const float* b3    = (const float*)d_in[12];
    const float* bn3w  = (const float*)d_in[13];
    const float* bn3b  = (const float*)d_in[14];

    float* out    = (float*)d_out;
    float* out_y  = out + 1;
    float* out_ye = out + 1 + N;
    float* out_xs = out + 1 + 2 * N;
    float* out_us = out_xs + (size_t)T * N * DIM;

    cudaFuncSetAttribute(persistK,
                         cudaFuncAttributeMaxDynamicSharedMemorySize,
                         SMF * (int)sizeof(float));

    transpose_dw<<<dim3(N * DIM / 32, 2), dim3(32, 8)>>>(dw);
    persistK<<<GRID, NT, SMF * sizeof(float)>>>(
        zinit, yinit, bn0w, bn0b, w1, bn1w, bn1b, w2, bn2w, bn2b,
        w3, b3, bn3w, bn3b, out, out_y, out_ye, out_xs, out_us);
}

// round 12
// speedup vs baseline: 1.5139x; 1.0643x over previous
#include <cuda_runtime.h>

// ---------------------------------------------------------------------------
// Problem constants + smem layout
// ---------------------------------------------------------------------------
namespace {
constexpr int   N    = 4096;
constexpr int   DIM  = 100;
constexpr int   HID  = 110;
constexpr int   T    = 50;
constexpr float DT   = 0.02f;
constexpr float EPS  = 1e-6f;
constexpr int   GRID = 128;       // co-resident blocks (1 per SM)
constexpr int   NT   = 512;       // threads per block
constexpr int   WS   = 112;       // weight tile col stride (16B aligned quads)
constexpr int   NG   = 8;         // stat reduction groups
constexpr int   PS   = 256;       // per-group stat stride (sum @0, sumsq @128)

// smem offsets in floats
constexpr int OF_W1 = 0;                    // [100][112]
constexpr int OF_W2 = OF_W1 + DIM * WS;     // [110][112]
constexpr int OF_W3 = OF_W2 + HID * WS;     // [110][112]
constexpr int OF_X  = OF_W3 + HID * WS;     // [100][34]  x state  [k][r]
constexpr int OF_A  = OF_X + DIM * 34;      // [110][34]  h1 / h3 tile
constexpr int OF_B  = OF_A + HID * 34;      // [110][34]  h2 tile
constexpr int OF_D  = OF_B + HID * 34;      // [110][64]  duplicated gemm input
constexpr int OF_Y  = OF_D + HID * 64;      // [32]       y state
constexpr int OF_AF = OF_Y + 32;            // [112] affine a
constexpr int OF_BF = OF_AF + 112;          // [112] affine c
// resident per-feature parameters (loaded once)
constexpr int OF_P0W = OF_BF + 112;         // bn0w [100]
constexpr int OF_P0B = OF_P0W + DIM;        // bn0b [100]
constexpr int OF_P1W = OF_P0B + DIM;        // bn1w [110]
constexpr int OF_P1B = OF_P1W + HID;        // bn1b [110]
constexpr int OF_P2W = OF_P1B + HID;        // bn2w [110]
constexpr int OF_P2B = OF_P2W + HID;        // bn2b [110]
constexpr int OF_P3W = OF_P2B + HID;        // bn3w [100]
constexpr int OF_P3B = OF_P3W + DIM;        // bn3b [100]
constexpr int OF_B3  = OF_P3B + DIM;        // b3   [100]
constexpr int OF_ZI  = OF_B3 + DIM;         // zinit[100]
constexpr int SMF    = OF_ZI + DIM;         // 55056 floats = 220224 bytes
}

// ---------------------------------------------------------------------------
// Global state — BN stats are NG group copies to cut atomic contention:
//   group copy g at gP[g*PS + k] (sum) / gP[g*PS + 128 + k] (sumsq)
// ---------------------------------------------------------------------------
__device__ float g_dwT[(size_t)T * N * DIM];   // dw transposed [T][N][DIM]
__device__ float g_p0[NG * PS];
__device__ float g_p1[NG * PS];
__device__ float g_p2[NG * PS];
__device__ float g_p3[NG * PS];
__device__ float g_acc[2];
__device__ unsigned g_cnt;
__device__ volatile unsigned g_gen;

__device__ __forceinline__ void affine_coef(float sum, float sumsq, float w,
                                            float b, float& a, float& c) {
    float mean = sum * (1.0f / N);
    float var  = fmaf(-mean, mean, sumsq * (1.0f / N)) + EPS;
    float r    = rsqrtf(var);
    r = r * (1.5f - 0.5f * var * r * r);   // Newton refine
    a = w * r;
    c = fmaf(-mean, a, b);
}

// sum the NG group partials for column k (pipelined L2 loads)
__device__ __forceinline__ float2 gather_stat(const float* __restrict__ gP,
                                              int k) {
    float s = 0.f, q = 0.f;
#pragma unroll
    for (int g = 0; g < NG; ++g) {
        s += __ldcg(&gP[g * PS + k]);
        q += __ldcg(&gP[g * PS + 128 + k]);
    }
    return make_float2(s, q);
}

// flat grid barrier (R6-proven): all GRID blocks resident by construction
__device__ __forceinline__ void gbar(unsigned& target) {
    __syncthreads();
    if (threadIdx.x == 0) {
        __threadfence();
        if (atomicAdd(&g_cnt, 1u) == (unsigned)(GRID - 1)) {
            atomicExch(&g_cnt, 0u);
            __threadfence();
            g_gen = target;
        } else {
            while (g_gen < target) { __nanosleep(32); }
        }
        __threadfence();
    }
    __syncthreads();
    ++target;
}

#define FMA2(acc, a, b) \
    asm("fma.rn.f32x2 %0, %1, %2, %0;" : "+l"(acc) : "l"(a), "l"(b))

// ---------------------------------------------------------------------------
// Transpose dw [N*DIM, T] -> [T, N*DIM]; block (0,0) also resets global state
// ---------------------------------------------------------------------------
__global__ void transpose_dw(const float* __restrict__ in) {
    __shared__ float s[32][33];
    const int tx = threadIdx.x, ty = threadIdx.y;
    const int tid = ty * 32 + tx;
    if (blockIdx.x == 0 && blockIdx.y == 0) {
        for (int k = tid; k < NG * PS; k += 256) {
            g_p0[k] = 0.f; g_p1[k] = 0.f; g_p2[k] = 0.f; g_p3[k] = 0.f;
        }
        if (tid == 0) { g_acc[0] = 0.f; g_acc[1] = 0.f; g_cnt = 0u; g_gen = 0u; }
    }
    const int ij0 = blockIdx.x * 32;
    const int t0  = blockIdx.y * 32;
#pragma unroll
    for (int i = 0; i < 32; i += 8) {
        int t = t0 + tx;
        int ij = ij0 + ty + i;
        if (t < T) s[ty + i][tx] = in[(size_t)ij * T + t];
    }
    __syncthreads();
#pragma unroll
    for (int i = 0; i < 32; i += 8) {
        int t = t0 + ty + i;
        int ij = ij0 + tx;
        if (t < T) g_dwT[(size_t)t * (N * DIM) + ij] = s[tx][ty + i];
    }
}

// ---------------------------------------------------------------------------
// BN affine (+relu) on [K x 32] tile -> interleaved duplicated layout:
//   chunks 0..7  = row pairs {0,1},{4,5},...,{28,29}
//   chunks 8..15 = row pairs {2,3},{6,7},...,{30,31}
// ---------------------------------------------------------------------------
template <int K, bool RELU>
__device__ __forceinline__ void prep(const float* __restrict__ gP,
                                     const float* __restrict__ bnw,
                                     const float* __restrict__ bnb,
                                     const float* __restrict__ src,
                                     float* __restrict__ dup,
                                     float* __restrict__ sAf,
                                     float* __restrict__ sBf) {
    const int tid = threadIdx.x;
    for (int k = tid; k < K; k += NT) {
        float2 sq = gather_stat(gP, k);
        float a, c;
        affine_coef(sq.x, sq.y, bnw[k], bnb[k], a, c);
        sAf[k] = a; sBf[k] = c;
    }
    __syncthreads();
    for (int idx = tid; idx < K * 32; idx += NT) {
        int k = idx >> 5, r = idx & 31;
        float v = fmaf(src[k * 34 + r], sAf[k], sBf[k]);
        if (RELU) v = fmaxf(v, 0.f);
        int off = ((r & 2) ? 32 : 0) + (r >> 2) * 4 + (r & 1) * 2;
        *reinterpret_cast<float2*>(dup + (k << 6) + off) = make_float2(v, v);
    }
    __syncthreads();
}

// ---------------------------------------------------------------------------
// GEMM: sO[c*34+r] = sum_k dup[k][r] * sW[k*WS+c]  (+ biasS[c] from smem)
// 7 active warps, lane tile 4 rows x 4 cols; float2-only epilogue stores.
// ---------------------------------------------------------------------------
template <int K, int C, bool BIAS>
__device__ __forceinline__ void gemm(const float* __restrict__ sD,
                                     const float* __restrict__ sW,
                                     float* __restrict__ sO,
                                     const float* __restrict__ biasS) {
    const int warp = threadIdx.x >> 5, lane = threadIdx.x & 31;
    if (warp >= 7) return;
    const int g  = lane & 7;                         // row group: rows 4g..4g+3
    const int c0 = warp * 16 + ((lane >> 3) << 2);   // 4 cols, c0+3 <= 111
    const int r0 = 4 * g;

    unsigned long long acc[4][2];
#pragma unroll
    for (int r = 0; r < 4; ++r) { acc[r][0] = 0ull; acc[r][1] = 0ull; }

    const float* pD = sD + 4 * g;            // chunk g
    const float* pW = sW + c0;
#pragma unroll 2
    for (int k = 0; k < K; ++k) {
        ulonglong2 xa = *reinterpret_cast<const ulonglong2*>(pD);
        ulonglong2 xb = *reinterpret_cast<const ulonglong2*>(pD + 32);
        ulonglong2 w  = *reinterpret_cast<const ulonglong2*>(pW);
        FMA2(acc[0][0], w.x, xa.x);
        FMA2(acc[0][1], w.y, xa.x);
        FMA2(acc[1][0], w.x, xa.y);
        FMA2(acc[1][1], w.y, xa.y);
        FMA2(acc[2][0], w.x, xb.x);
        FMA2(acc[2][1], w.y, xb.x);
        FMA2(acc[3][0], w.x, xb.y);
        FMA2(acc[3][1], w.y, xb.y);
        pD += 64;
        pW += WS;
    }

    float v[4][4];
#pragma unroll
    for (int r = 0; r < 4; ++r) {
        asm("mov.b64 {%0,%1}, %2;" : "=f"(v[r][0]), "=f"(v[r][1]) : "l"(acc[r][0]));
        asm("mov.b64 {%0,%1}, %2;" : "=f"(v[r][2]), "=f"(v[r][3]) : "l"(acc[r][1]));
    }
#pragma unroll
    for (int c = 0; c < 4; ++c) {
        const int col = c0 + c;
        if (col < C) {
            float b = BIAS ? biasS[col] : 0.f;
            float* dst = &sO[col * 34 + r0];           // even offset: 8B aligned
            *reinterpret_cast<float2*>(dst)     = make_float2(v[0][c] + b, v[1][c] + b);
            *reinterpret_cast<float2*>(dst + 2) = make_float2(v[2][c] + b, v[3][c] + b);
        }
    }
}

// per-column sum / sumsq over [C x 32] tile -> this block's group stat copy
template <int C>
__device__ __forceinline__ void statp(const float* __restrict__ sO,
                                      float* __restrict__ gP) {
    const int tid = threadIdx.x;
    float* base = gP + (blockIdx.x & (NG - 1)) * PS;
    if (tid < C) {
        float s = 0.f, q = 0.f;
#pragma unroll
        for (int r = 0; r < 32; r += 2) {
            float2 v = *reinterpret_cast<const float2*>(&sO[tid * 34 + r]);
            s += v.x + v.y;
            q = fmaf(v.x, v.x, fmaf(v.y, v.y, q));
        }
        atomicAdd(&base[tid], s);
        atomicAdd(&base[128 + tid], q);
    }
}

// ---------------------------------------------------------------------------
// The persistent kernel: all 50 steps in one launch
// ---------------------------------------------------------------------------
__global__ void __launch_bounds__(NT, 1) persistK(
    const float* __restrict__ zinit, const float* __restrict__ yinit,
    const float* __restrict__ bn0w, const float* __restrict__ bn0b,
    const float* __restrict__ w1,   const float* __restrict__ bn1w,
    const float* __restrict__ bn1b, const float* __restrict__ w2,
    const float* __restrict__ bn2w, const float* __restrict__ bn2b,
    const float* __restrict__ w3,   const float* __restrict__ b3,
    const float* __restrict__ bn3w, const float* __restrict__ bn3b,
    float* __restrict__ out_loss, float* __restrict__ out_y,
    float* __restrict__ out_ye,   float* __restrict__ out_xs,
    float* __restrict__ out_us)
{
    extern __shared__ float sm[];
    float* sW1 = sm + OF_W1;
    float* sW2 = sm + OF_W2;
    float* sW3 = sm + OF_W3;
    float* sX  = sm + OF_X;
    float* sTa = sm + OF_A;
    float* sTb = sm + OF_B;
    float* sD  = sm + OF_D;
    float* sy  = sm + OF_Y;
    float* sAf = sm + OF_AF;
    float* sBf = sm + OF_BF;

    const int tid   = threadIdx.x;
    const int warp  = tid >> 5, lane = tid & 31;
    const int rbase = blockIdx.x * 32;
    unsigned target = 1;

    // zero weight region (pads) + x state
    for (int i = tid; i < OF_X; i += NT) sm[i] = 0.f;
    for (int i = tid; i < DIM * 34; i += NT) sX[i] = 0.f;
    __syncthreads();
    // load weights once: sW[k*WS + c] = W[c*K + k]
    for (int idx = tid; idx < HID * DIM; idx += NT) {   // W1 [110,100]
        int c = idx / DIM, k = idx - c * DIM;
        sW1[k * WS + c] = w1[idx];
    }
    for (int idx = tid; idx < HID * HID; idx += NT) {   // W2 [110,110]
        int c = idx / HID, k = idx - c * HID;
        sW2[k * WS + c] = w2[idx];
    }
    for (int idx = tid; idx < DIM * HID; idx += NT) {   // W3 [100,110]
        int c = idx / HID, k = idx - c * HID;
        sW3[k * WS + c] = w3[idx];
    }
    // resident per-feature params (loaded once)
    if (tid < DIM) {
        sm[OF_P0W + tid] = bn0w[tid];
        sm[OF_P0B + tid] = bn0b[tid];
        sm[OF_P3W + tid] = bn3w[tid];
        sm[OF_P3B + tid] = bn3b[tid];
        sm[OF_B3  + tid] = b3[tid];
        sm[OF_ZI  + tid] = zinit[tid];
    } else if (tid >= 128 && tid < 128 + HID) {
        int k = tid - 128;
        sm[OF_P1W + k] = bn1w[k];
        sm[OF_P1B + k] = bn1b[k];
    } else if (tid >= 256 && tid < 256 + HID) {
        int k = tid - 256;
        sm[OF_P2W + k] = bn2w[k];
        sm[OF_P2B + k] = bn2b[k];
    }
    const float y0 = yinit[0];

    for (int t = 0; t < T; ++t) {
        const bool first = (t == 0), last = (t == T - 1);

        // ---------------- phase A ----------------
        if (!first) {
            for (int k = tid; k < DIM; k += NT) {
                float2 sq = gather_stat(g_p3, k);
                float a, c;
                affine_coef(sq.x, sq.y, sm[OF_P3W + k], sm[OF_P3B + k], a, c);
                sAf[k] = a * 1e-4f;   // /DIM (subnet) * /DIM (z update)
                sBf[k] = c * 1e-4f;
            }
        }
        if (!last && blockIdx.x == 0)
            for (int k = tid; k < NG * PS; k += NT) __stcg(&g_p2[k], 0.f);
        __syncthreads();

        const float* dwt = g_dwT + ((size_t)t * N + rbase) * DIM;
        float* xsO = out_xs + ((size_t)t * N + rbase) * DIM;

#pragma unroll
        for (int it = 0; it < 2; ++it) {
            const int r = it * 16 + warp;
            const int i = rbase + r;
            float sz = 0.f, zdw = 0.f, xx = 0.f;
            float xo[4], dwv[4];
#pragma unroll
            for (int c2 = 0; c2 < 4; ++c2) {
                int j = lane + 32 * c2;
                xo[c2] = 0.f; dwv[c2] = 0.f;
                if (j < DIM) {
                    float z = first ? sm[OF_ZI + j]
                                    : fmaf(sTa[j * 34 + r], sAf[j], sBf[j]);
                    dwv[c2] = dwt[(size_t)r * DIM + j];
                    xo[c2]  = sX[j * 34 + r];
                    sz  += z;
                    zdw += z * dwv[c2];
                    xx  += xo[c2] * xo[c2];
                }
            }
#pragma unroll
            for (int o = 16; o; o >>= 1) {
                sz  += __shfl_xor_sync(~0u, sz, o);
                zdw += __shfl_xor_sync(~0u, zdw, o);
                xx  += __shfl_xor_sync(~0u, xx, o);
            }
            const float u = fminf(fmaxf(-sz, -1.f), 1.f);
            float yv = first ? y0 : sy[r];
            yv = yv - DT * 0.5f * (xx + u * u) + DT * sz * u + zdw;
            if (lane == 0) {
                out_us[(size_t)t * N + i] = u;
                if (last) {
                    out_y[i] = yv;
                    float ye = 0.5f * xx;
                    out_ye[i] = ye;
                    float d = yv - ye, ad = fabsf(d);
                    atomicAdd(&g_acc[0], (ad < 1.f) ? 0.5f * d * d : ad - 0.5f);
                    atomicAdd(&g_acc[1], ye);
                } else {
                    sy[r] = yv;
                }
            }
#pragma unroll
            for (int c2 = 0; c2 < 4; ++c2) {
                int j = lane + 32 * c2;
                if (j < DIM) {
                    xsO[(size_t)r * DIM + j] = xo[c2];
                    if (!last)
                        sX[j * 34 + r] = fmaf(xo[c2], 1.f - DT,
                                              fmaf(u, DT, dwv[c2]));
                }
            }
        }
        __syncthreads();

        if (last) {
            gbar(target);
            if (blockIdx.x == 0 && tid == 0) {
                float m1 = __ldcg(&g_acc[0]) * (1.0f / N);
                float m2 = __ldcg(&g_acc[1]) * (1.0f / N);
                out_loss[0] = 100.0f * (m1 + m2 * m2);
            }
            break;
        }

        statp<DIM>(sX, g_p0);
        gbar(target);

        // ---------------- GEMM1: h1 = bn0(x) @ W1^T ----------------
        if (blockIdx.x == 0)
            for (int k = tid; k < NG * PS; k += NT) __stcg(&g_p3[k], 0.f);
        prep<DIM, false>(g_p0, sm + OF_P0W, sm + OF_P0B, sX, sD, sAf, sBf);
        gemm<DIM, HID, false>(sD, sW1, sTa, nullptr);
        __syncthreads();
        statp<HID>(sTa, g_p1);
        gbar(target);

        // ---------------- GEMM2: h2 = relu(bn1(h1)) @ W2^T ----------------
        if (blockIdx.x == 0)
            for (int k = tid; k < NG * PS; k += NT) __stcg(&g_p0[k], 0.f);
        prep<HID, true>(g_p1, sm + OF_P1W, sm + OF_P1B, sTa, sD, sAf, sBf);
        gemm<HID, HID, false>(sD, sW2, sTb, nullptr);
        __syncthreads();
        statp<HID>(sTb, g_p2);
        gbar(target);

        // ---------------- GEMM3: h3 = relu(bn2(h2)) @ W3^T + b3 --------
        if (blockIdx.x == 0)
            for (int k = tid; k < NG * PS; k += NT) __stcg(&g_p1[k], 0.f);
        prep<HID, true>(g_p2, sm + OF_P2W, sm + OF_P2B, sTb, sD, sAf, sBf);
        gemm<HID, DIM, true>(sD, sW3, sTa, sm + OF_B3);
        __syncthreads();
        statp<DIM>(sTa, g_p3);
        gbar(target);
    }
}

// ---------------------------------------------------------------------------
// Launcher
// ---------------------------------------------------------------------------
extern "C" void kernel_launch(void* const* d_in, const int* in_sizes, int n_in,
                              void* d_out, int out_size) {
    const float* dw    = (const float*)d_in[0];
    const float* yinit = (const float*)d_in[1];
    const float* zinit = (const float*)d_in[2];
    const float* bn0w  = (const float*)d_in[3];
    const float* bn0b  = (const float*)d_in[4];
    const float* w1    = (const float*)d_in[5];
    const float* bn1w  = (const float*)d_in[6];
    const float* bn1b  = (const float*)d_in[7];
    const float* w2    = (const float*)d_in[8];
    const float* bn2w  = (const float*)d_in[9];
    const float* bn2b  = (const float*)d_in[10];
    const float* w3    = (const float*)d_in[11];
    const float* b3    = (const float*)d_in[12];
    const float* bn3w  = (const float*)d_in[13];
    const float* bn3b  = (const float*)d_in[14];

    float* out    = (float*)d_out;
    float* out_y  = out + 1;
    float* out_ye = out + 1 + N;
    float* out_xs = out + 1 + 2 * N;
    float* out_us = out_xs + (size_t)T * N * DIM;

    cudaFuncSetAttribute(persistK,
                         cudaFuncAttributeMaxDynamicSharedMemorySize,
                         SMF * (int)sizeof(float));

    transpose_dw<<<dim3(N * DIM / 32, 2), dim3(32, 8)>>>(dw);
    persistK<<<GRID, NT, SMF * sizeof(float)>>>(
        zinit, yinit, bn0w, bn0b, w1, bn1w, bn1b, w2, bn2w, bn2b,
        w3, b3, bn3w, bn3b, out, out_y, out_ye, out_xs, out_us);
}

// round 13
// speedup vs baseline: 1.5883x; 1.0491x over previous
#include <cuda_runtime.h>

// ---------------------------------------------------------------------------
// Problem constants + smem layout
// ---------------------------------------------------------------------------
namespace {
constexpr int   N    = 4096;
constexpr int   DIM  = 100;
constexpr int   HID  = 110;
constexpr int   T    = 50;
constexpr float DT   = 0.02f;
constexpr float EPS  = 1e-6f;
constexpr int   GRID = 128;       // co-resident blocks (1 per SM)
constexpr int   NT   = 512;       // threads per block
constexpr int   WS   = 112;       // weight tile col stride (16B aligned quads)
constexpr int   NG   = 8;         // stat reduction groups
constexpr int   PS   = 256;       // per-group stat stride (sum @0, sumsq @128)

// smem offsets in floats
constexpr int OF_W1 = 0;                    // [100][112]
constexpr int OF_W2 = OF_W1 + DIM * WS;     // [110][112]
constexpr int OF_W3 = OF_W2 + HID * WS;     // [110][112]
constexpr int OF_X  = OF_W3 + HID * WS;     // [100][34]  x state  [k][r]
constexpr int OF_A  = OF_X + DIM * 34;      // [110][34]  h1 / h3 tile
constexpr int OF_B  = OF_A + HID * 34;      // [110][34]  h2 tile
constexpr int OF_D  = OF_B + HID * 34;      // [110][64]  duplicated gemm input
constexpr int OF_Y  = OF_D + HID * 64;      // [32]       y state
constexpr int OF_AF = OF_Y + 32;            // [112] affine a
constexpr int OF_BF = OF_AF + 112;          // [112] affine c
// resident per-feature parameters (loaded once)
constexpr int OF_P0W = OF_BF + 112;         // bn0w [100]
constexpr int OF_P0B = OF_P0W + DIM;        // bn0b [100]
constexpr int OF_P1W = OF_P0B + DIM;        // bn1w [110]
constexpr int OF_P1B = OF_P1W + HID;        // bn1b [110]
constexpr int OF_P2W = OF_P1B + HID;        // bn2w [110]
constexpr int OF_P2B = OF_P2W + HID;        // bn2b [110]
constexpr int OF_P3W = OF_P2B + HID;        // bn3w [100]
constexpr int OF_P3B = OF_P3W + DIM;        // bn3b [100]
constexpr int OF_B3  = OF_P3B + DIM;        // b3   [100]
constexpr int OF_ZI  = OF_B3 + DIM;         // zinit[100]
constexpr int SMF    = OF_ZI + DIM;         // 55056 floats = 220224 bytes
}

// ---------------------------------------------------------------------------
// Global state — BN stats are NG group copies to cut atomic contention:
//   group copy g at gP[g*PS + k] (sum) / gP[g*PS + 128 + k] (sumsq)
// ---------------------------------------------------------------------------
__device__ float g_dwT[(size_t)T * N * DIM];   // dw transposed [T][N][DIM]
__device__ float g_p0[NG * PS];
__device__ float g_p1[NG * PS];
__device__ float g_p2[NG * PS];
__device__ float g_p3[NG * PS];
__device__ float g_acc[2];
__device__ unsigned g_cnt;        // monotonic barrier counter (reset per launch)

__device__ __forceinline__ void affine_coef(float sum, float sumsq, float w,
                                            float b, float& a, float& c) {
    float mean = sum * (1.0f / N);
    float var  = fmaf(-mean, mean, sumsq * (1.0f / N)) + EPS;
    float r    = rsqrtf(var);
    r = r * (1.5f - 0.5f * var * r * r);   // Newton refine
    a = w * r;
    c = fmaf(-mean, a, b);
}

// sum the NG group partials for column k (pipelined L2 loads)
__device__ __forceinline__ float2 gather_stat(const float* __restrict__ gP,
                                              int k) {
    float s = 0.f, q = 0.f;
#pragma unroll
    for (int g = 0; g < NG; ++g) {
        s += __ldcg(&gP[g * PS + k]);
        q += __ldcg(&gP[g * PS + 128 + k]);
    }
    return make_float2(s, q);
}

// grid barrier: monotonic counter, fire-and-forget REDG arrival, direct
// acquire-poll on the counter. No reset, no releaser thread, no extra hop.
// Barrier n is complete when cnt >= n*GRID. target starts at GRID.
__device__ __forceinline__ void gbar(unsigned& target) {
    __syncthreads();
    if (threadIdx.x == 0) {
        __threadfence();
        asm volatile("red.release.gpu.global.add.u32 [%0], 1;"
                     :: "l"(&g_cnt) : "memory");
        unsigned cur;
        do {
            asm volatile("ld.acquire.gpu.global.u32 %0, [%1];"
                         : "=r"(cur) : "l"(&g_cnt) : "memory");
        } while (cur < target);
        __threadfence();
    }
    __syncthreads();
    target += GRID;
}

#define FMA2(acc, a, b) \
    asm("fma.rn.f32x2 %0, %1, %2, %0;" : "+l"(acc) : "l"(a), "l"(b))

// ---------------------------------------------------------------------------
// Transpose dw [N*DIM, T] -> [T, N*DIM]; block (0,0) also resets global state
// ---------------------------------------------------------------------------
__global__ void transpose_dw(const float* __restrict__ in) {
    __shared__ float s[32][33];
    const int tx = threadIdx.x, ty = threadIdx.y;
    const int tid = ty * 32 + tx;
    if (blockIdx.x == 0 && blockIdx.y == 0) {
        for (int k = tid; k < NG * PS; k += 256) {
            g_p0[k] = 0.f; g_p1[k] = 0.f; g_p2[k] = 0.f; g_p3[k] = 0.f;
        }
        if (tid == 0) { g_acc[0] = 0.f; g_acc[1] = 0.f; g_cnt = 0u; }
    }
    const int ij0 = blockIdx.x * 32;
    const int t0  = blockIdx.y * 32;
#pragma unroll
    for (int i = 0; i < 32; i += 8) {
        int t = t0 + tx;
        int ij = ij0 + ty + i;
        if (t < T) s[ty + i][tx] = in[(size_t)ij * T + t];
    }
    __syncthreads();
#pragma unroll
    for (int i = 0; i < 32; i += 8) {
        int t = t0 + ty + i;
        int ij = ij0 + tx;
        if (t < T) g_dwT[(size_t)t * (N * DIM) + ij] = s[tx][ty + i];
    }
}

// ---------------------------------------------------------------------------
// BN affine (+relu) on [K x 32] tile -> interleaved duplicated layout:
//   chunks 0..7  = row pairs {0,1},{4,5},...,{28,29}
//   chunks 8..15 = row pairs {2,3},{6,7},...,{30,31}
// ---------------------------------------------------------------------------
template <int K, bool RELU>
__device__ __forceinline__ void prep(const float* __restrict__ gP,
                                     const float* __restrict__ bnw,
                                     const float* __restrict__ bnb,
                                     const float* __restrict__ src,
                                     float* __restrict__ dup,
                                     float* __restrict__ sAf,
                                     float* __restrict__ sBf) {
    const int tid = threadIdx.x;
    for (int k = tid; k < K; k += NT) {
        float2 sq = gather_stat(gP, k);
        float a, c;
        affine_coef(sq.x, sq.y, bnw[k], bnb[k], a, c);
        sAf[k] = a; sBf[k] = c;
    }
    __syncthreads();
    for (int idx = tid; idx < K * 32; idx += NT) {
        int k = idx >> 5, r = idx & 31;
        float v = fmaf(src[k * 34 + r], sAf[k], sBf[k]);
        if (RELU) v = fmaxf(v, 0.f);
        int off = ((r & 2) ? 32 : 0) + (r >> 2) * 4 + (r & 1) * 2;
        *reinterpret_cast<float2*>(dup + (k << 6) + off) = make_float2(v, v);
    }
    __syncthreads();
}

// ---------------------------------------------------------------------------
// GEMM: sO[c*34+r] = sum_k dup[k][r] * sW[k*WS+c]  (+ biasS[c] from smem)
// 7 active warps, lane tile 4 rows x 4 cols; float2-only epilogue stores.
// ---------------------------------------------------------------------------
template <int K, int C, bool BIAS>
__device__ __forceinline__ void gemm(const float* __restrict__ sD,
                                     const float* __restrict__ sW,
                                     float* __restrict__ sO,
                                     const float* __restrict__ biasS) {
    const int warp = threadIdx.x >> 5, lane = threadIdx.x & 31;
    if (warp >= 7) return;
    const int g  = lane & 7;                         // row group: rows 4g..4g+3
    const int c0 = warp * 16 + ((lane >> 3) << 2);   // 4 cols, c0+3 <= 111
    const int r0 = 4 * g;

    unsigned long long acc[4][2];
#pragma unroll
    for (int r = 0; r < 4; ++r) { acc[r][0] = 0ull; acc[r][1] = 0ull; }

    const float* pD = sD + 4 * g;            // chunk g
    const float* pW = sW + c0;
#pragma unroll 2
    for (int k = 0; k < K; ++k) {
        ulonglong2 xa = *reinterpret_cast<const ulonglong2*>(pD);
        ulonglong2 xb = *reinterpret_cast<const ulonglong2*>(pD + 32);
        ulonglong2 w  = *reinterpret_cast<const ulonglong2*>(pW);
        FMA2(acc[0][0], w.x, xa.x);
        FMA2(acc[0][1], w.y, xa.x);
        FMA2(acc[1][0], w.x, xa.y);
        FMA2(acc[1][1], w.y, xa.y);
        FMA2(acc[2][0], w.x, xb.x);
        FMA2(acc[2][1], w.y, xb.x);
        FMA2(acc[3][0], w.x, xb.y);
        FMA2(acc[3][1], w.y, xb.y);
        pD += 64;
        pW += WS;
    }

    float v[4][4];
#pragma unroll
    for (int r = 0; r < 4; ++r) {
        asm("mov.b64 {%0,%1}, %2;" : "=f"(v[r][0]), "=f"(v[r][1]) : "l"(acc[r][0]));
        asm("mov.b64 {%0,%1}, %2;" : "=f"(v[r][2]), "=f"(v[r][3]) : "l"(acc[r][1]));
    }
#pragma unroll
    for (int c = 0; c < 4; ++c) {
        const int col = c0 + c;
        if (col < C) {
            float b = BIAS ? biasS[col] : 0.f;
            float* dst = &sO[col * 34 + r0];           // even offset: 8B aligned
            *reinterpret_cast<float2*>(dst)     = make_float2(v[0][c] + b, v[1][c] + b);
            *reinterpret_cast<float2*>(dst + 2) = make_float2(v[2][c] + b, v[3][c] + b);
        }
    }
}

// per-column sum / sumsq over [C x 32] tile -> this block's group stat copy
template <int C>
__device__ __forceinline__ void statp(const float* __restrict__ sO,
                                      float* __restrict__ gP) {
    const int tid = threadIdx.x;
    float* base = gP + (blockIdx.x & (NG - 1)) * PS;
    if (tid < C) {
        float s = 0.f, q = 0.f;
#pragma unroll
        for (int r = 0; r < 32; r += 2) {
            float2 v = *reinterpret_cast<const float2*>(&sO[tid * 34 + r]);
            s += v.x + v.y;
            q = fmaf(v.x, v.x, fmaf(v.y, v.y, q));
        }
        atomicAdd(&base[tid], s);
        atomicAdd(&base[128 + tid], q);
    }
}

// ---------------------------------------------------------------------------
// The persistent kernel: all 50 steps in one launch
// ---------------------------------------------------------------------------
__global__ void __launch_bounds__(NT, 1) persistK(
    const float* __restrict__ zinit, const float* __restrict__ yinit,
    const float* __restrict__ bn0w, const float* __restrict__ bn0b,
    const float* __restrict__ w1,   const float* __restrict__ bn1w,
    const float* __restrict__ bn1b, const float* __restrict__ w2,
    const float* __restrict__ bn2w, const float* __restrict__ bn2b,
    const float* __restrict__ w3,   const float* __restrict__ b3,
    const float* __restrict__ bn3w, const float* __restrict__ bn3b,
    float* __restrict__ out_loss, float* __restrict__ out_y,
    float* __restrict__ out_ye,   float* __restrict__ out_xs,
    float* __restrict__ out_us)
{
    extern __shared__ float sm[];
    float* sW1 = sm + OF_W1;
    float* sW2 = sm + OF_W2;
    float* sW3 = sm + OF_W3;
    float* sX  = sm + OF_X;
    float* sTa = sm + OF_A;
    float* sTb = sm + OF_B;
    float* sD  = sm + OF_D;
    float* sy  = sm + OF_Y;
    float* sAf = sm + OF_AF;
    float* sBf = sm + OF_BF;

    const int tid   = threadIdx.x;
    const int warp  = tid >> 5, lane = tid & 31;
    const int rbase = blockIdx.x * 32;
    unsigned target = GRID;

    // zero weight region (pads) + x state
    for (int i = tid; i < OF_X; i += NT) sm[i] = 0.f;
    for (int i = tid; i < DIM * 34; i += NT) sX[i] = 0.f;
    __syncthreads();
    // load weights once: sW[k*WS + c] = W[c*K + k]
    for (int idx = tid; idx < HID * DIM; idx += NT) {   // W1 [110,100]
        int c = idx / DIM, k = idx - c * DIM;
        sW1[k * WS + c] = w1[idx];
    }
    for (int idx = tid; idx < HID * HID; idx += NT) {   // W2 [110,110]
        int c = idx / HID, k = idx - c * HID;
        sW2[k * WS + c] = w2[idx];
    }
    for (int idx = tid; idx < DIM * HID; idx += NT) {   // W3 [100,110]
        int c = idx / HID, k = idx - c * HID;
        sW3[k * WS + c] = w3[idx];
    }
    // resident per-feature params (loaded once)
    if (tid < DIM) {
        sm[OF_P0W + tid] = bn0w[tid];
        sm[OF_P0B + tid] = bn0b[tid];
        sm[OF_P3W + tid] = bn3w[tid];
        sm[OF_P3B + tid] = bn3b[tid];
        sm[OF_B3  + tid] = b3[tid];
        sm[OF_ZI  + tid] = zinit[tid];
    } else if (tid >= 128 && tid < 128 + HID) {
        int k = tid - 128;
        sm[OF_P1W + k] = bn1w[k];
        sm[OF_P1B + k] = bn1b[k];
    } else if (tid >= 256 && tid < 256 + HID) {
        int k = tid - 256;
        sm[OF_P2W + k] = bn2w[k];
        sm[OF_P2B + k] = bn2b[k];
    }
    const float y0 = yinit[0];

    for (int t = 0; t < T; ++t) {
        const bool first = (t == 0), last = (t == T - 1);

        // ---------------- phase A ----------------
        if (!first) {
            for (int k = tid; k < DIM; k += NT) {
                float2 sq = gather_stat(g_p3, k);
                float a, c;
                affine_coef(sq.x, sq.y, sm[OF_P3W + k], sm[OF_P3B + k], a, c);
                sAf[k] = a * 1e-4f;   // /DIM (subnet) * /DIM (z update)
                sBf[k] = c * 1e-4f;
            }
        }
        if (!last && blockIdx.x == 0)
            for (int k = tid; k < NG * PS; k += NT) __stcg(&g_p2[k], 0.f);
        __syncthreads();

        const float* dwt = g_dwT + ((size_t)t * N + rbase) * DIM;
        float* xsO = out_xs + ((size_t)t * N + rbase) * DIM;

#pragma unroll
        for (int it = 0; it < 2; ++it) {
            const int r = it * 16 + warp;
            const int i = rbase + r;
            float sz = 0.f, zdw = 0.f, xx = 0.f;
            float xo[4], dwv[4];
#pragma unroll
            for (int c2 = 0; c2 < 4; ++c2) {
                int j = lane + 32 * c2;
                xo[c2] = 0.f; dwv[c2] = 0.f;
                if (j < DIM) {
                    float z = first ? sm[OF_ZI + j]
                                    : fmaf(sTa[j * 34 + r], sAf[j], sBf[j]);
                    dwv[c2] = dwt[(size_t)r * DIM + j];
                    xo[c2]  = sX[j * 34 + r];
                    sz  += z;
                    zdw += z * dwv[c2];
                    xx  += xo[c2] * xo[c2];
                }
            }
#pragma unroll
            for (int o = 16; o; o >>= 1) {
                sz  += __shfl_xor_sync(~0u, sz, o);
                zdw += __shfl_xor_sync(~0u, zdw, o);
                xx  += __shfl_xor_sync(~0u, xx, o);
            }
            const float u = fminf(fmaxf(-sz, -1.f), 1.f);
            float yv = first ? y0 : sy[r];
            yv = yv - DT * 0.5f * (xx + u * u) + DT * sz * u + zdw;
            if (lane == 0) {
                out_us[(size_t)t * N + i] = u;
                if (last) {
                    out_y[i] = yv;
                    float ye = 0.5f * xx;
                    out_ye[i] = ye;
                    float d = yv - ye, ad = fabsf(d);
                    atomicAdd(&g_acc[0], (ad < 1.f) ? 0.5f * d * d : ad - 0.5f);
                    atomicAdd(&g_acc[1], ye);
                } else {
                    sy[r] = yv;
                }
            }
#pragma unroll
            for (int c2 = 0; c2 < 4; ++c2) {
                int j = lane + 32 * c2;
                if (j < DIM) {
                    xsO[(size_t)r * DIM + j] = xo[c2];
                    if (!last)
                        sX[j * 34 + r] = fmaf(xo[c2], 1.f - DT,
                                              fmaf(u, DT, dwv[c2]));
                }
            }
        }
        __syncthreads();

        if (last) {
            gbar(target);
            if (blockIdx.x == 0 && tid == 0) {
                float m1 = __ldcg(&g_acc[0]) * (1.0f / N);
                float m2 = __ldcg(&g_acc[1]) * (1.0f / N);
                out_loss[0] = 100.0f * (m1 + m2 * m2);
            }
            break;
        }

        statp<DIM>(sX, g_p0);
        gbar(target);

        // ---------------- GEMM1: h1 = bn0(x) @ W1^T ----------------
        if (blockIdx.x == 0)
            for (int k = tid; k < NG * PS; k += NT) __stcg(&g_p3[k], 0.f);
        prep<DIM, false>(g_p0, sm + OF_P0W, sm + OF_P0B, sX, sD, sAf, sBf);
        gemm<DIM, HID, false>(sD, sW1, sTa, nullptr);
        __syncthreads();
        statp<HID>(sTa, g_p1);
        gbar(target);

        // ---------------- GEMM2: h2 = relu(bn1(h1)) @ W2^T ----------------
        if (blockIdx.x == 0)
            for (int k = tid; k < NG * PS; k += NT) __stcg(&g_p0[k], 0.f);
        prep<HID, true>(g_p1, sm + OF_P1W, sm + OF_P1B, sTa, sD, sAf, sBf);
        gemm<HID, HID, false>(sD, sW2, sTb, nullptr);
        __syncthreads();
        statp<HID>(sTb, g_p2);
        gbar(target);

        // ---------------- GEMM3: h3 = relu(bn2(h2)) @ W3^T + b3 --------
        if (blockIdx.x == 0)
            for (int k = tid; k < NG * PS; k += NT) __stcg(&g_p1[k], 0.f);
        prep<HID, true>(g_p2, sm + OF_P2W, sm + OF_P2B, sTb, sD, sAf, sBf);
        gemm<HID, DIM, true>(sD, sW3, sTa, sm + OF_B3);
        __syncthreads();
        statp<DIM>(sTa, g_p3);
        gbar(target);
    }
}

// ---------------------------------------------------------------------------
// Launcher
// ---------------------------------------------------------------------------
extern "C" void kernel_launch(void* const* d_in, const int* in_sizes, int n_in,
                              void* d_out, int out_size) {
    const float* dw    = (const float*)d_in[0];
    const float* yinit = (const float*)d_in[1];
    const float* zinit = (const float*)d_in[2];
    const float* bn0w  = (const float*)d_in[3];
    const float* bn0b  = (const float*)d_in[4];
    const float* w1    = (const float*)d_in[5];
    const float* bn1w  = (const float*)d_in[6];
    const float* bn1b  = (const float*)d_in[7];
    const float* w2    = (const float*)d_in[8];
    const float* bn2w  = (const float*)d_in[9];
    const float* bn2b  = (const float*)d_in[10];
    const float* w3    = (const float*)d_in[11];
    const float* b3    = (const float*)d_in[12];
    const float* bn3w  = (const float*)d_in[13];
    const float* bn3b  = (const float*)d_in[14];

    float* out    = (float*)d_out;
    float* out_y  = out + 1;
    float* out_ye = out + 1 + N;
    float* out_xs = out + 1 + 2 * N;
    float* out_us = out_xs + (size_t)T * N * DIM;

    cudaFuncSetAttribute(persistK,
                         cudaFuncAttributeMaxDynamicSharedMemorySize,
                         SMF * (int)sizeof(float));

    transpose_dw<<<dim3(N * DIM / 32, 2), dim3(32, 8)>>>(dw);
    persistK<<<GRID, NT, SMF * sizeof(float)>>>(
        zinit, yinit, bn0w, bn0b, w1, bn1w, bn1b, w2, bn2w, bn2b,
        w3, b3, bn3w, bn3b, out, out_y, out_ye, out_xs, out_us);
}

// round 14
// speedup vs baseline: 1.7201x; 1.0830x over previous
#include <cuda_runtime.h>

// ---------------------------------------------------------------------------
// Problem constants + smem layout
// ---------------------------------------------------------------------------
namespace {
constexpr int   N    = 4096;
constexpr int   DIM  = 100;
constexpr int   HID  = 110;
constexpr int   T    = 50;
constexpr float DT   = 0.02f;
constexpr float EPS  = 1e-6f;
constexpr int   GRID = 128;       // co-resident blocks (1 per SM)
constexpr int   NT   = 512;       // threads per block
constexpr int   WS   = 112;       // weight tile col stride (16B aligned quads)
constexpr int   NG   = 8;         // stat reduction groups
constexpr int   PS   = 256;       // per-group stat stride (sum @0, sumsq @128)

// smem offsets in floats
constexpr int OF_W1 = 0;                    // [100][112]
constexpr int OF_W2 = OF_W1 + DIM * WS;     // [110][112]
constexpr int OF_W3 = OF_W2 + HID * WS;     // [110][112]
constexpr int OF_X  = OF_W3 + HID * WS;     // [100][34]  x state  [k][r]
constexpr int OF_A  = OF_X + DIM * 34;      // [110][34]  h1 / h3 tile
constexpr int OF_B  = OF_A + HID * 34;      // [110][34]  h2 tile
constexpr int OF_D  = OF_B + HID * 34;      // [110][64]  duplicated gemm input
constexpr int OF_Y  = OF_D + HID * 64;      // [32]       y state
constexpr int OF_AF = OF_Y + 32;            // [112] affine a
constexpr int OF_BF = OF_AF + 112;          // [112] affine c
// resident per-feature parameters (loaded once)
constexpr int OF_P0W = OF_BF + 112;         // bn0w [100]
constexpr int OF_P0B = OF_P0W + DIM;        // bn0b [100]
constexpr int OF_P1W = OF_P0B + DIM;        // bn1w [110]
constexpr int OF_P1B = OF_P1W + HID;        // bn1b [110]
constexpr int OF_P2W = OF_P1B + HID;        // bn2w [110]
constexpr int OF_P2B = OF_P2W + HID;        // bn2b [110]
constexpr int OF_P3W = OF_P2B + HID;        // bn3w [100]
constexpr int OF_P3B = OF_P3W + DIM;        // bn3b [100]
constexpr int OF_B3  = OF_P3B + DIM;        // b3   [100]
constexpr int OF_ZI  = OF_B3 + DIM;         // zinit[100]
constexpr int SMF    = OF_ZI + DIM;         // 55056 floats = 220224 bytes
}

// ---------------------------------------------------------------------------
// Global state — BN stats are NG group copies to cut atomic contention:
//   group copy g at gP[g*PS + k] (sum) / gP[g*PS + 128 + k] (sumsq)
// ---------------------------------------------------------------------------
__device__ float g_dwT[(size_t)T * N * DIM];   // dw transposed [T][N][DIM]
__device__ float g_p0[NG * PS];
__device__ float g_p1[NG * PS];
__device__ float g_p2[NG * PS];
__device__ float g_p3[NG * PS];
__device__ float g_acc[2];
__device__ unsigned g_cnt;        // monotonic barrier counter (reset per launch)

__device__ __forceinline__ void affine_coef(float sum, float sumsq, float w,
                                            float b, float& a, float& c) {
    float mean = sum * (1.0f / N);
    float var  = fmaf(-mean, mean, sumsq * (1.0f / N)) + EPS;
    float r    = rsqrtf(var);
    r = r * (1.5f - 0.5f * var * r * r);   // Newton refine
    a = w * r;
    c = fmaf(-mean, a, b);
}

// sum the NG group partials for column k (pipelined L2 loads)
__device__ __forceinline__ float2 gather_stat(const float* __restrict__ gP,
                                              int k) {
    float s = 0.f, q = 0.f;
#pragma unroll
    for (int g = 0; g < NG; ++g) {
        s += __ldcg(&gP[g * PS + k]);
        q += __ldcg(&gP[g * PS + 128 + k]);
    }
    return make_float2(s, q);
}

// grid barrier (R13-proven protocol), split into arrive/wait so latency-bound
// work (global stores / prefetch loads) can issue inside the barrier idle.
__device__ __forceinline__ void gbar_arrive() {
    __syncthreads();
    if (threadIdx.x == 0) {
        __threadfence();
        asm volatile("red.release.gpu.global.add.u32 [%0], 1;"
                     :: "l"(&g_cnt) : "memory");
    }
}
__device__ __forceinline__ void gbar_wait(unsigned& target) {
    if (threadIdx.x == 0) {
        unsigned cur;
        do {
            asm volatile("ld.acquire.gpu.global.u32 %0, [%1];"
                         : "=r"(cur) : "l"(&g_cnt) : "memory");
        } while (cur < target);
        __threadfence();
    }
    __syncthreads();
    target += GRID;
}
__device__ __forceinline__ void gbar(unsigned& target) {
    gbar_arrive();
    gbar_wait(target);
}

#define FMA2(acc, a, b) \
    asm("fma.rn.f32x2 %0, %1, %2, %0;" : "+l"(acc) : "l"(a), "l"(b))

// ---------------------------------------------------------------------------
// Transpose dw [N*DIM, T] -> [T, N*DIM]; block (0,0) also resets global state
// ---------------------------------------------------------------------------
__global__ void transpose_dw(const float* __restrict__ in) {
    __shared__ float s[32][33];
    const int tx = threadIdx.x, ty = threadIdx.y;
    const int tid = ty * 32 + tx;
    if (blockIdx.x == 0 && blockIdx.y == 0) {
        for (int k = tid; k < NG * PS; k += 256) {
            g_p0[k] = 0.f; g_p1[k] = 0.f; g_p2[k] = 0.f; g_p3[k] = 0.f;
        }
        if (tid == 0) { g_acc[0] = 0.f; g_acc[1] = 0.f; g_cnt = 0u; }
    }
    const int ij0 = blockIdx.x * 32;
    const int t0  = blockIdx.y * 32;
#pragma unroll
    for (int i = 0; i < 32; i += 8) {
        int t = t0 + tx;
        int ij = ij0 + ty + i;
        if (t < T) s[ty + i][tx] = in[(size_t)ij * T + t];
    }
    __syncthreads();
#pragma unroll
    for (int i = 0; i < 32; i += 8) {
        int t = t0 + ty + i;
        int ij = ij0 + tx;
        if (t < T) g_dwT[(size_t)t * (N * DIM) + ij] = s[tx][ty + i];
    }
}

// ---------------------------------------------------------------------------
// BN affine (+relu) on [K x 32] tile -> interleaved duplicated layout:
//   chunks 0..7  = row pairs {0,1},{4,5},...,{28,29}
//   chunks 8..15 = row pairs {2,3},{6,7},...,{30,31}
// ---------------------------------------------------------------------------
template <int K, bool RELU>
__device__ __forceinline__ void prep(const float* __restrict__ gP,
                                     const float* __restrict__ bnw,
                                     const float* __restrict__ bnb,
                                     const float* __restrict__ src,
                                     float* __restrict__ dup,
                                     float* __restrict__ sAf,
                                     float* __restrict__ sBf) {
    const int tid = threadIdx.x;
    for (int k = tid; k < K; k += NT) {
        float2 sq = gather_stat(gP, k);
        float a, c;
        affine_coef(sq.x, sq.y, bnw[k], bnb[k], a, c);
        sAf[k] = a; sBf[k] = c;
    }
    __syncthreads();
    for (int idx = tid; idx < K * 32; idx += NT) {
        int k = idx >> 5, r = idx & 31;
        float v = fmaf(src[k * 34 + r], sAf[k], sBf[k]);
        if (RELU) v = fmaxf(v, 0.f);
        int off = ((r & 2) ? 32 : 0) + (r >> 2) * 4 + (r & 1) * 2;
        *reinterpret_cast<float2*>(dup + (k << 6) + off) = make_float2(v, v);
    }
    __syncthreads();
}

// ---------------------------------------------------------------------------
// GEMM: sO[c*34+r] = sum_k dup[k][r] * sW[k*WS+c]  (+ biasS[c] from smem)
// 7 active warps, lane tile 4 rows x 4 cols; float2-only epilogue stores.
// ---------------------------------------------------------------------------
template <int K, int C, bool BIAS>
__device__ __forceinline__ void gemm(const float* __restrict__ sD,
                                     const float* __restrict__ sW,
                                     float* __restrict__ sO,
                                     const float* __restrict__ biasS) {
    const int warp = threadIdx.x >> 5, lane = threadIdx.x & 31;
    if (warp >= 7) return;
    const int g  = lane & 7;                         // row group: rows 4g..4g+3
    const int c0 = warp * 16 + ((lane >> 3) << 2);   // 4 cols, c0+3 <= 111
    const int r0 = 4 * g;

    unsigned long long acc[4][2];
#pragma unroll
    for (int r = 0; r < 4; ++r) { acc[r][0] = 0ull; acc[r][1] = 0ull; }

    const float* pD = sD + 4 * g;            // chunk g
    const float* pW = sW + c0;
#pragma unroll 4
    for (int k = 0; k < K; ++k) {
        ulonglong2 xa = *reinterpret_cast<const ulonglong2*>(pD);
        ulonglong2 xb = *reinterpret_cast<const ulonglong2*>(pD + 32);
        ulonglong2 w  = *reinterpret_cast<const ulonglong2*>(pW);
        FMA2(acc[0][0], w.x, xa.x);
        FMA2(acc[0][1], w.y, xa.x);
        FMA2(acc[1][0], w.x, xa.y);
        FMA2(acc[1][1], w.y, xa.y);
        FMA2(acc[2][0], w.x, xb.x);
        FMA2(acc[2][1], w.y, xb.x);
        FMA2(acc[3][0], w.x, xb.y);
        FMA2(acc[3][1], w.y, xb.y);
        pD += 64;
        pW += WS;
    }

    float v[4][4];
#pragma unroll
    for (int r = 0; r < 4; ++r) {
        asm("mov.b64 {%0,%1}, %2;" : "=f"(v[r][0]), "=f"(v[r][1]) : "l"(acc[r][0]));
        asm("mov.b64 {%0,%1}, %2;" : "=f"(v[r][2]), "=f"(v[r][3]) : "l"(acc[r][1]));
    }
#pragma unroll
    for (int c = 0; c < 4; ++c) {
        const int col = c0 + c;
        if (col < C) {
            float b = BIAS ? biasS[col] : 0.f;
            float* dst = &sO[col * 34 + r0];           // even offset: 8B aligned
            *reinterpret_cast<float2*>(dst)     = make_float2(v[0][c] + b, v[1][c] + b);
            *reinterpret_cast<float2*>(dst + 2) = make_float2(v[2][c] + b, v[3][c] + b);
        }
    }
}

// per-column sum / sumsq over [C x 32] tile -> this block's group stat copy
template <int C>
__device__ __forceinline__ void statp(const float* __restrict__ sO,
                                      float* __restrict__ gP) {
    const int tid = threadIdx.x;
    float* base = gP + (blockIdx.x & (NG - 1)) * PS;
    if (tid < C) {
        float s = 0.f, q = 0.f;
#pragma unroll
        for (int r = 0; r < 32; r += 2) {
            float2 v = *reinterpret_cast<const float2*>(&sO[tid * 34 + r]);
            s += v.x + v.y;
            q = fmaf(v.x, v.x, fmaf(v.y, v.y, q));
        }
        atomicAdd(&base[tid], s);
        atomicAdd(&base[128 + tid], q);
    }
}

// ---------------------------------------------------------------------------
// The persistent kernel: all 50 steps in one launch
// ---------------------------------------------------------------------------
__global__ void __launch_bounds__(NT, 1) persistK(
    const float* __restrict__ zinit, const float* __restrict__ yinit,
    const float* __restrict__ bn0w, const float* __restrict__ bn0b,
    const float* __restrict__ w1,   const float* __restrict__ bn1w,
    const float* __restrict__ bn1b, const float* __restrict__ w2,
    const float* __restrict__ bn2w, const float* __restrict__ bn2b,
    const float* __restrict__ w3,   const float* __restrict__ b3,
    const float* __restrict__ bn3w, const float* __restrict__ bn3b,
    float* __restrict__ out_loss, float* __restrict__ out_y,
    float* __restrict__ out_ye,   float* __restrict__ out_xs,
    float* __restrict__ out_us)
{
    extern __shared__ float sm[];
    float* sW1 = sm + OF_W1;
    float* sW2 = sm + OF_W2;
    float* sW3 = sm + OF_W3;
    float* sX  = sm + OF_X;
    float* sTa = sm + OF_A;
    float* sTb = sm + OF_B;
    float* sD  = sm + OF_D;
    float* sy  = sm + OF_Y;
    float* sAf = sm + OF_AF;
    float* sBf = sm + OF_BF;

    const int tid   = threadIdx.x;
    const int warp  = tid >> 5, lane = tid & 31;
    const int rbase = blockIdx.x * 32;
    unsigned target = GRID;

    // zero weight region (pads) + x state
    for (int i = tid; i < OF_X; i += NT) sm[i] = 0.f;
    for (int i = tid; i < DIM * 34; i += NT) sX[i] = 0.f;
    __syncthreads();
    // load weights once: sW[k*WS + c] = W[c*K + k]
    for (int idx = tid; idx < HID * DIM; idx += NT) {   // W1 [110,100]
        int c = idx / DIM, k = idx - c * DIM;
        sW1[k * WS + c] = w1[idx];
    }
    for (int idx = tid; idx < HID * HID; idx += NT) {   // W2 [110,110]
        int c = idx / HID, k = idx - c * HID;
        sW2[k * WS + c] = w2[idx];
    }
    for (int idx = tid; idx < DIM * HID; idx += NT) {   // W3 [100,110]
        int c = idx / HID, k = idx - c * HID;
        sW3[k * WS + c] = w3[idx];
    }
    // resident per-feature params (loaded once)
    if (tid < DIM) {
        sm[OF_P0W + tid] = bn0w[tid];
        sm[OF_P0B + tid] = bn0b[tid];
        sm[OF_P3W + tid] = bn3w[tid];
        sm[OF_P3B + tid] = bn3b[tid];
        sm[OF_B3  + tid] = b3[tid];
        sm[OF_ZI  + tid] = zinit[tid];
    } else if (tid >= 128 && tid < 128 + HID) {
        int k = tid - 128;
        sm[OF_P1W + k] = bn1w[k];
        sm[OF_P1B + k] = bn1b[k];
    } else if (tid >= 256 && tid < 256 + HID) {
        int k = tid - 256;
        sm[OF_P2W + k] = bn2w[k];
        sm[OF_P2B + k] = bn2b[k];
    }
    const float y0 = yinit[0];

    // prefetch dw tile for step 0 (rows it*16+warp, cols lane+32c2)
    float dwv[2][4];
    {
        const float* dw0 = g_dwT + (size_t)rbase * DIM;
#pragma unroll
        for (int it = 0; it < 2; ++it) {
            const int r = it * 16 + warp;
#pragma unroll
            for (int c2 = 0; c2 < 4; ++c2) {
                int j = lane + 32 * c2;
                dwv[it][c2] = (j < DIM) ? dw0[(size_t)r * DIM + j] : 0.f;
            }
        }
    }
    float xov[2][4];   // x_t values held for deferred xs store

    for (int t = 0; t < T; ++t) {
        const bool first = (t == 0), last = (t == T - 1);

        // ---------------- phase A ----------------
        if (!first) {
            for (int k = tid; k < DIM; k += NT) {
                float2 sq = gather_stat(g_p3, k);
                float a, c;
                affine_coef(sq.x, sq.y, sm[OF_P3W + k], sm[OF_P3B + k], a, c);
                sAf[k] = a * 1e-4f;   // /DIM (subnet) * /DIM (z update)
                sBf[k] = c * 1e-4f;
            }
        }
        if (!last && blockIdx.x == 0)
            for (int k = tid; k < NG * PS; k += NT) __stcg(&g_p2[k], 0.f);
        __syncthreads();

        float* xsO = out_xs + ((size_t)t * N + rbase) * DIM;

#pragma unroll
        for (int it = 0; it < 2; ++it) {
            const int r = it * 16 + warp;
            const int i = rbase + r;
            float sz = 0.f, zdw = 0.f, xx = 0.f;
            float xo[4];
#pragma unroll
            for (int c2 = 0; c2 < 4; ++c2) {
                int j = lane + 32 * c2;
                xo[c2] = 0.f;
                if (j < DIM) {
                    float z = first ? sm[OF_ZI + j]
                                    : fmaf(sTa[j * 34 + r], sAf[j], sBf[j]);
                    xo[c2] = sX[j * 34 + r];
                    sz  += z;
                    zdw += z * dwv[it][c2];
                    xx  += xo[c2] * xo[c2];
                }
            }
#pragma unroll
            for (int o = 16; o; o >>= 1) {
                sz  += __shfl_xor_sync(~0u, sz, o);
                zdw += __shfl_xor_sync(~0u, zdw, o);
                xx  += __shfl_xor_sync(~0u, xx, o);
            }
            const float u = fminf(fmaxf(-sz, -1.f), 1.f);
            float yv = first ? y0 : sy[r];
            yv = yv - DT * 0.5f * (xx + u * u) + DT * sz * u + zdw;
            if (lane == 0) {
                out_us[(size_t)t * N + i] = u;
                if (last) {
                    out_y[i] = yv;
                    float ye = 0.5f * xx;
                    out_ye[i] = ye;
                    float d = yv - ye, ad = fabsf(d);
                    atomicAdd(&g_acc[0], (ad < 1.f) ? 0.5f * d * d : ad - 0.5f);
                    atomicAdd(&g_acc[1], ye);
                } else {
                    sy[r] = yv;
                }
            }
#pragma unroll
            for (int c2 = 0; c2 < 4; ++c2) {
                int j = lane + 32 * c2;
                if (j < DIM) {
                    if (last) {
                        xsO[(size_t)r * DIM + j] = xo[c2];   // final step: store now
                    } else {
                        xov[it][c2] = xo[c2];                // defer store
                        sX[j * 34 + r] = fmaf(xo[c2], 1.f - DT,
                                              fmaf(u, DT, dwv[it][c2]));
                    }
                }
            }
        }
        __syncthreads();

        if (last) {
            gbar(target);
            if (blockIdx.x == 0 && tid == 0) {
                float m1 = __ldcg(&g_acc[0]) * (1.0f / N);
                float m2 = __ldcg(&g_acc[1]) * (1.0f / N);
                out_loss[0] = 100.0f * (m1 + m2 * m2);
            }
            break;
        }

        statp<DIM>(sX, g_p0);
        gbar_arrive();
        // deferred xs stores issue inside the barrier idle
#pragma unroll
        for (int it = 0; it < 2; ++it) {
            const int r = it * 16 + warp;
#pragma unroll
            for (int c2 = 0; c2 < 4; ++c2) {
                int j = lane + 32 * c2;
                if (j < DIM) xsO[(size_t)r * DIM + j] = xov[it][c2];
            }
        }
        gbar_wait(target);

        // ---------------- GEMM1: h1 = bn0(x) @ W1^T ----------------
        if (blockIdx.x == 0)
            for (int k = tid; k < NG * PS; k += NT) __stcg(&g_p3[k], 0.f);
        prep<DIM, false>(g_p0, sm + OF_P0W, sm + OF_P0B, sX, sD, sAf, sBf);
        gemm<DIM, HID, false>(sD, sW1, sTa, nullptr);
        __syncthreads();
        statp<HID>(sTa, g_p1);
        gbar(target);

        // ---------------- GEMM2: h2 = relu(bn1(h1)) @ W2^T ----------------
        if (blockIdx.x == 0)
            for (int k = tid; k < NG * PS; k += NT) __stcg(&g_p0[k], 0.f);
        prep<HID, true>(g_p1, sm + OF_P1W, sm + OF_P1B, sTa, sD, sAf, sBf);
        gemm<HID, HID, false>(sD, sW2, sTb, nullptr);
        __syncthreads();
        statp<HID>(sTb, g_p2);
        gbar(target);

        // ---------------- GEMM3: h3 = relu(bn2(h2)) @ W3^T + b3 --------
        if (blockIdx.x == 0)
            for (int k = tid; k < NG * PS; k += NT) __stcg(&g_p1[k], 0.f);
        prep<HID, true>(g_p2, sm + OF_P2W, sm + OF_P2B, sTb, sD, sAf, sBf);
        gemm<HID, DIM, true>(sD, sW3, sTa, sm + OF_B3);
        __syncthreads();
        statp<DIM>(sTa, g_p3);
        gbar_arrive();
        // prefetch next step's dw tile inside the barrier idle (DRAM latency)
        {
            const float* dwn = g_dwT + ((size_t)(t + 1) * N + rbase) * DIM;
#pragma unroll
            for (int it = 0; it < 2; ++it) {
                const int r = it * 16 + warp;
#pragma unroll
                for (int c2 = 0; c2 < 4; ++c2) {
                    int j = lane + 32 * c2;
                    dwv[it][c2] = (j < DIM) ? dwn[(size_t)r * DIM + j] : 0.f;
                }
            }
        }
        gbar_wait(target);
    }
}

// ---------------------------------------------------------------------------
// Launcher
// ---------------------------------------------------------------------------
extern "C" void kernel_launch(void* const* d_in, const int* in_sizes, int n_in,
                              void* d_out, int out_size) {
    const float* dw    = (const float*)d_in[0];
    const float* yinit = (const float*)d_in[1];
    const float* zinit = (const float*)d_in[2];
    const float* bn0w  = (const float*)d_in[3];
    const float* bn0b  = (const float*)d_in[4];
    const float* w1    = (const float*)d_in[5];
    const float* bn1w  = (const float*)d_in[6];
    const float* bn1b  = (const float*)d_in[7];
    const float* w2    = (const float*)d_in[8];
    const float* bn2w  = (const float*)d_in[9];
    const float* bn2b  = (const float*)d_in[10];
    const float* w3    = (const float*)d_in[11];
    const float* b3    = (const float*)d_in[12];
    const float* bn3w  = (const float*)d_in[13];
    const float* bn3b  = (const float*)d_in[14];

    float* out    = (float*)d_out;
    float* out_y  = out + 1;
    float* out_ye = out + 1 + N;
    float* out_xs = out + 1 + 2 * N;
    float* out_us = out_xs + (size_t)T * N * DIM;

    cudaFuncSetAttribute(persistK,
                         cudaFuncAttributeMaxDynamicSharedMemorySize,
                         SMF * (int)sizeof(float));

    transpose_dw<<<dim3(N * DIM / 32, 2), dim3(32, 8)>>>(dw);
    persistK<<<GRID, NT, SMF * sizeof(float)>>>(
        zinit, yinit, bn0w, bn0b, w1, bn1w, bn1b, w2, bn2w, bn2b,
        w3, b3, bn3w, bn3b, out, out_y, out_ye, out_xs, out_us);
}